// round 2
// baseline (speedup 1.0000x reference)
#include <cuda_runtime.h>

#define BB    2
#define HH    48
#define WW    48
#define CC    256
#define NHEAD 8
#define HD    32
#define LL    (HH*WW)      /* 2304 */
#define MTOT  (BB*LL)      /* 4608 */

// ---------------- scratch (device globals; no allocs allowed) ----------------
__device__ float g_q   [BB*NHEAD*LL*HD];   // head-major [b][n][l][hd]
__device__ float g_k   [BB*NHEAD*LL*HD];
__device__ float g_vh  [BB*NHEAD*LL*HD];   // V head-major
__device__ float g_vn  [BB*LL*CC];         // V in NHWC (for depthwise conv)
__device__ float g_lepe[BB*LL*CC];
__device__ float g_attn[BB*LL*CC];         // attention out, [b][l][c]

// ---------------- QKV projection GEMM: 4608x256 @ 256x256, z in {q,k,v} -----
__global__ __launch_bounds__(256) void qkv_gemm(
    const float* __restrict__ x,
    const float* __restrict__ wq, const float* __restrict__ bq,
    const float* __restrict__ wk, const float* __restrict__ bk,
    const float* __restrict__ wv, const float* __restrict__ bv)
{
    const int z = blockIdx.z;
    const float* Wm   = (z == 0) ? wq : (z == 1) ? wk : wv;
    const float* bias = (z == 0) ? bq : (z == 1) ? bk : bv;

    __shared__ __align__(16) float As[8][132];
    __shared__ __align__(16) float Bs[8][128];

    const int t  = threadIdx.x;
    const int m0 = blockIdx.y * 128;
    const int n0 = blockIdx.x * 128;
    const int tr = t >> 4;        // 0..15 row group
    const int tc = t & 15;        // 0..15 col group

    float acc[8][8];
    #pragma unroll
    for (int i = 0; i < 8; i++)
        #pragma unroll
        for (int j = 0; j < 8; j++) acc[i][j] = 0.f;

    const int la_m = t >> 1;            // 0..127
    const int la_k = (t & 1) * 4;       // 0 or 4
    const int lb_k = t >> 5;            // 0..7
    const int lb_n = (t & 31) * 4;      // 0..124

    for (int k0 = 0; k0 < CC; k0 += 8) {
        float4 av  = *(const float4*)&x [(m0 + la_m)*CC + k0 + la_k];
        float4 bv4 = *(const float4*)&Wm[(k0 + lb_k)*CC + n0 + lb_n];
        __syncthreads();
        As[la_k+0][la_m] = av.x; As[la_k+1][la_m] = av.y;
        As[la_k+2][la_m] = av.z; As[la_k+3][la_m] = av.w;
        *(float4*)&Bs[lb_k][lb_n] = bv4;
        __syncthreads();
        #pragma unroll
        for (int kk = 0; kk < 8; kk++) {
            float a[8], b[8];
            *(float4*)&a[0] = *(float4*)&As[kk][tr*8];
            *(float4*)&a[4] = *(float4*)&As[kk][tr*8+4];
            *(float4*)&b[0] = *(float4*)&Bs[kk][tc*8];
            *(float4*)&b[4] = *(float4*)&Bs[kk][tc*8+4];
            #pragma unroll
            for (int i = 0; i < 8; i++)
                #pragma unroll
                for (int j = 0; j < 8; j++)
                    acc[i][j] += a[i] * b[j];
        }
    }

    const float scaling = 0.17677669529663687f; /* 32^-0.5 */
    #pragma unroll
    for (int i = 0; i < 8; i++) {
        int m  = m0 + tr*8 + i;
        int bi = m / LL, l = m % LL;
        #pragma unroll
        for (int j = 0; j < 8; j++) {
            int c  = n0 + tc*8 + j;
            float v = acc[i][j] + bias[c];
            if (z == 1) v *= scaling;
            int n = c >> 5, d = c & 31;
            int idx = ((bi*NHEAD + n)*LL + l)*HD + d;
            if (z == 0)      g_q[idx] = v;
            else if (z == 1) g_k[idx] = v;
            else { g_vh[idx] = v; g_vn[(bi*LL + l)*CC + c] = v; }
        }
    }
}

// ---------------- rotary on q,k in place --------------------------------------
__global__ void rotary_kernel(const float* __restrict__ sinv,
                              const float* __restrict__ cosv)
{
    int idx = blockIdx.x * blockDim.x + threadIdx.x;   // float4 group id
    const int total = BB*NHEAD*LL*(HD/4);
    if (idx >= total) return;
    int d4 = idx & 7;
    int l  = (idx >> 3) % LL;
    int base = idx * 4;
    int sidx = l*HD + d4*4;
    float4 s = *(const float4*)&sinv[sidx];
    float4 c = *(const float4*)&cosv[sidx];

    float4 q = *(float4*)&g_q[base];
    float4 k = *(float4*)&g_k[base];
    float4 qo, ko;
    qo.x = q.x*c.x - q.y*s.x;  qo.y = q.y*c.y + q.x*s.y;
    qo.z = q.z*c.z - q.w*s.z;  qo.w = q.w*c.w + q.z*s.w;
    ko.x = k.x*c.x - k.y*s.x;  ko.y = k.y*c.y + k.x*s.y;
    ko.z = k.z*c.z - k.w*s.z;  ko.w = k.w*c.w + k.z*s.w;
    *(float4*)&g_q[base] = qo;
    *(float4*)&g_k[base] = ko;
}

// ---------------- 5x5 depthwise conv (LEPE) -----------------------------------
__global__ __launch_bounds__(256) void lepe_conv(const float* __restrict__ wdw,
                                                 const float* __restrict__ bdw)
{
    int c = threadIdx.x;
    int p = blockIdx.x;                 // 0..BB*LL-1
    int bi = p / LL; int l = p % LL;
    int h = l / WW, w = l % WW;
    float acc = bdw[c];
    #pragma unroll
    for (int dy = 0; dy < 5; dy++) {
        int hy = h + dy - 2;
        if (hy < 0 || hy >= HH) continue;
        #pragma unroll
        for (int dx = 0; dx < 5; dx++) {
            int wx = w + dx - 2;
            if (wx < 0 || wx >= WW) continue;
            acc += g_vn[(bi*LL + hy*WW + wx)*CC + c] * wdw[(dy*5+dx)*CC + c];
        }
    }
    g_lepe[p*CC + c] = acc;
}

// ---------------- flash attention (fp32 SIMT) ---------------------------------
#define AROWS 16
#define ATN   64
__device__ __forceinline__ float warp_max(float v) {
    #pragma unroll
    for (int o = 16; o; o >>= 1) v = fmaxf(v, __shfl_xor_sync(0xffffffffu, v, o));
    return v;
}
__device__ __forceinline__ float warp_sum(float v) {
    #pragma unroll
    for (int o = 16; o; o >>= 1) v += __shfl_xor_sync(0xffffffffu, v, o);
    return v;
}

__global__ __launch_bounds__(256) void attn_kernel(const float* __restrict__ mask)
{
    __shared__ __align__(16) float q_sh[AROWS][HD];
    __shared__ __align__(16) float Ksh[ATN][36];
    __shared__ __align__(16) float Vsh[ATN][36];
    __shared__ __align__(16) float Psh[8][ATN][2];   // [warp][key][row]

    const int bi   = blockIdx.x;             // batch (fastest -> mask L2 reuse)
    const int l0   = blockIdx.y * AROWS;
    const int n    = blockIdx.z;
    const int t    = threadIdx.x;
    const int lane = t & 31, warp = t >> 5;

    const int bn = bi*NHEAD + n;
    const float* qg = g_q  + bn*LL*HD;
    const float* kg = g_k  + bn*LL*HD;
    const float* vg = g_vh + bn*LL*HD;

    // load Q rows into shared
    {
        int i = t * 2;
        int r = i >> 5, d = i & 31;
        *(float2*)&q_sh[r][d] = *(const float2*)&qg[(l0 + r)*HD + d];
    }

    const int r0 = warp*2, r1 = r0 + 1;
    const int row0 = l0 + r0, row1 = l0 + r1;
    const float* mrow0 = mask + ((size_t)n*LL + row0)*LL;
    const float* mrow1 = mask + ((size_t)n*LL + row1)*LL;

    float rm0 = -1e30f, rm1 = -1e30f;     // running max
    float sum0 = 0.f,  sum1 = 0.f;        // running denom
    float o0 = 0.f,    o1 = 0.f;          // output accum (d = lane)

    const int lj = t >> 2;                // 0..63
    const int ld = (t & 3) * 8;           // 0,8,16,24

    for (int j0 = 0; j0 < LL; j0 += ATN) {
        float4 k1 = *(const float4*)&kg[(j0+lj)*HD + ld];
        float4 k2 = *(const float4*)&kg[(j0+lj)*HD + ld + 4];
        float4 v1 = *(const float4*)&vg[(j0+lj)*HD + ld];
        float4 v2 = *(const float4*)&vg[(j0+lj)*HD + ld + 4];
        __syncthreads();
        *(float4*)&Ksh[lj][ld]   = k1;  *(float4*)&Ksh[lj][ld+4] = k2;
        *(float4*)&Vsh[lj][ld]   = v1;  *(float4*)&Vsh[lj][ld+4] = v2;
        __syncthreads();

        float s[2][2];
        #pragma unroll
        for (int kk = 0; kk < 2; kk++) {
            int j = kk*32 + lane;
            float s0 = 0.f, s1 = 0.f;
            #pragma unroll
            for (int i = 0; i < 8; i++) {
                float4 kv = *(float4*)&Ksh[j][i*4];
                float4 q0 = *(float4*)&q_sh[r0][i*4];
                float4 q1 = *(float4*)&q_sh[r1][i*4];
                s0 += q0.x*kv.x + q0.y*kv.y + q0.z*kv.z + q0.w*kv.w;
                s1 += q1.x*kv.x + q1.y*kv.y + q1.z*kv.z + q1.w*kv.w;
            }
            s0 += __ldg(&mrow0[j0 + j]);
            s1 += __ldg(&mrow1[j0 + j]);
            s[kk][0] = s0; s[kk][1] = s1;
        }

        float tm0 = warp_max(fmaxf(s[0][0], s[1][0]));
        float tm1 = warp_max(fmaxf(s[0][1], s[1][1]));
        float nm0 = fmaxf(rm0, tm0), nm1 = fmaxf(rm1, tm1);
        float c0 = __expf(rm0 - nm0), c1 = __expf(rm1 - nm1);
        float p00 = __expf(s[0][0] - nm0), p10 = __expf(s[1][0] - nm0);
        float p01 = __expf(s[0][1] - nm1), p11 = __expf(s[1][1] - nm1);
        float ts0 = warp_sum(p00 + p10);
        float ts1 = warp_sum(p01 + p11);
        sum0 = sum0*c0 + ts0;  sum1 = sum1*c1 + ts1;
        o0 *= c0;  o1 *= c1;
        rm0 = nm0; rm1 = nm1;

        Psh[warp][lane     ][0] = p00;  Psh[warp][lane     ][1] = p01;
        Psh[warp][lane + 32][0] = p10;  Psh[warp][lane + 32][1] = p11;
        __syncwarp();
        #pragma unroll 4
        for (int j = 0; j < ATN; j++) {
            float2 p = *(float2*)&Psh[warp][j][0];
            float vv = Vsh[j][lane];
            o0 += p.x * vv;
            o1 += p.y * vv;
        }
        __syncwarp();
    }

    o0 /= sum0;  o1 /= sum1;
    g_attn[(bi*LL + row0)*CC + n*HD + lane] = o0;
    g_attn[(bi*LL + row1)*CC + n*HD + lane] = o1;
}

// ---------------- output GEMM: (attn + lepe) @ wo + bo ------------------------
__global__ __launch_bounds__(256) void out_gemm(const float* __restrict__ wo,
                                                const float* __restrict__ bo,
                                                float* __restrict__ out)
{
    __shared__ __align__(16) float As[8][132];
    __shared__ __align__(16) float Bs[8][128];

    const int t  = threadIdx.x;
    const int m0 = blockIdx.y * 128;
    const int n0 = blockIdx.x * 128;
    const int tr = t >> 4, tc = t & 15;

    float acc[8][8];
    #pragma unroll
    for (int i = 0; i < 8; i++)
        #pragma unroll
        for (int j = 0; j < 8; j++) acc[i][j] = 0.f;

    const int la_m = t >> 1, la_k = (t & 1) * 4;
    const int lb_k = t >> 5, lb_n = (t & 31) * 4;

    for (int k0 = 0; k0 < CC; k0 += 8) {
        float4 a1 = *(const float4*)&g_attn[(m0 + la_m)*CC + k0 + la_k];
        float4 a2 = *(const float4*)&g_lepe[(m0 + la_m)*CC + k0 + la_k];
        float4 av = make_float4(a1.x+a2.x, a1.y+a2.y, a1.z+a2.z, a1.w+a2.w);
        float4 bv4 = *(const float4*)&wo[(k0 + lb_k)*CC + n0 + lb_n];
        __syncthreads();
        As[la_k+0][la_m] = av.x; As[la_k+1][la_m] = av.y;
        As[la_k+2][la_m] = av.z; As[la_k+3][la_m] = av.w;
        *(float4*)&Bs[lb_k][lb_n] = bv4;
        __syncthreads();
        #pragma unroll
        for (int kk = 0; kk < 8; kk++) {
            float a[8], b[8];
            *(float4*)&a[0] = *(float4*)&As[kk][tr*8];
            *(float4*)&a[4] = *(float4*)&As[kk][tr*8+4];
            *(float4*)&b[0] = *(float4*)&Bs[kk][tc*8];
            *(float4*)&b[4] = *(float4*)&Bs[kk][tc*8+4];
            #pragma unroll
            for (int i = 0; i < 8; i++)
                #pragma unroll
                for (int j = 0; j < 8; j++)
                    acc[i][j] += a[i] * b[j];
        }
    }

    #pragma unroll
    for (int i = 0; i < 8; i++) {
        int m = m0 + tr*8 + i;
        #pragma unroll
        for (int j = 0; j < 8; j += 4) {
            int c = n0 + tc*8 + j;
            float4 v;
            v.x = acc[i][j+0] + bo[c+0];
            v.y = acc[i][j+1] + bo[c+1];
            v.z = acc[i][j+2] + bo[c+2];
            v.w = acc[i][j+3] + bo[c+3];
            *(float4*)&out[m*CC + c] = v;
        }
    }
}

// ---------------- launch -------------------------------------------------------
extern "C" void kernel_launch(void* const* d_in, const int* in_sizes, int n_in,
                              void* d_out, int out_size)
{
    const float* x    = (const float*)d_in[0];
    const float* sinv = (const float*)d_in[1];
    const float* cosv = (const float*)d_in[2];
    const float* mask = (const float*)d_in[3];
    const float* wq   = (const float*)d_in[4];
    const float* bq   = (const float*)d_in[5];
    const float* wk   = (const float*)d_in[6];
    const float* bk   = (const float*)d_in[7];
    const float* wv   = (const float*)d_in[8];
    const float* bv   = (const float*)d_in[9];
    const float* wdw  = (const float*)d_in[10];
    const float* bdw  = (const float*)d_in[11];
    const float* wo   = (const float*)d_in[12];
    const float* bo   = (const float*)d_in[13];
    float* out = (float*)d_out;

    qkv_gemm<<<dim3(CC/128, MTOT/128, 3), 256>>>(x, wq, bq, wk, bk, wv, bv);

    int rot_threads = BB*NHEAD*LL*(HD/4);
    rotary_kernel<<<(rot_threads + 255)/256, 256>>>(sinv, cosv);

    lepe_conv<<<BB*LL, 256>>>(wdw, bdw);

    attn_kernel<<<dim3(BB, LL/AROWS, NHEAD), 256>>>(mask);

    out_gemm<<<dim3(CC/128, MTOT/128), 256>>>(wo, bo, out);
}

// round 3
// speedup vs baseline: 2.4026x; 2.4026x over previous
#include <cuda_runtime.h>

#define BB    2
#define HH    48
#define WW    48
#define CC    256
#define NHEAD 8
#define HD    32
#define LL    (HH*WW)      /* 2304 */
#define MTOT  (BB*LL)      /* 4608 */

// ---------------- scratch (device globals; no allocs allowed) ----------------
__device__ float g_q   [BB*NHEAD*LL*HD];   // head-major [b][n][l][hd] (rotary applied)
__device__ float g_k   [BB*NHEAD*LL*HD];
__device__ float g_vh  [BB*NHEAD*LL*HD];   // V head-major
__device__ float g_vn  [BB*LL*CC];         // V in NHWC (for depthwise conv)
__device__ float g_lepe[BB*LL*CC];
__device__ float g_attn[BB*LL*CC];         // attention out, [b][l][c]

// ---------------- QKV projection GEMM + fused rotary --------------------------
__global__ __launch_bounds__(256) void qkv_gemm(
    const float* __restrict__ x,
    const float* __restrict__ wq, const float* __restrict__ bq,
    const float* __restrict__ wk, const float* __restrict__ bk,
    const float* __restrict__ wv, const float* __restrict__ bv,
    const float* __restrict__ sinv, const float* __restrict__ cosv)
{
    const int z = blockIdx.z;
    const float* Wm   = (z == 0) ? wq : (z == 1) ? wk : wv;
    const float* bias = (z == 0) ? bq : (z == 1) ? bk : bv;

    __shared__ __align__(16) float As[8][132];
    __shared__ __align__(16) float Bs[8][128];

    const int t  = threadIdx.x;
    const int m0 = blockIdx.y * 128;
    const int n0 = blockIdx.x * 128;
    const int tr = t >> 4;        // 0..15 row group
    const int tc = t & 15;        // 0..15 col group

    float acc[8][8];
    #pragma unroll
    for (int i = 0; i < 8; i++)
        #pragma unroll
        for (int j = 0; j < 8; j++) acc[i][j] = 0.f;

    const int la_m = t >> 1;            // 0..127
    const int la_k = (t & 1) * 4;       // 0 or 4
    const int lb_k = t >> 5;            // 0..7
    const int lb_n = (t & 31) * 4;      // 0..124

    for (int k0 = 0; k0 < CC; k0 += 8) {
        float4 av  = *(const float4*)&x [(m0 + la_m)*CC + k0 + la_k];
        float4 bv4 = *(const float4*)&Wm[(k0 + lb_k)*CC + n0 + lb_n];
        __syncthreads();
        As[la_k+0][la_m] = av.x; As[la_k+1][la_m] = av.y;
        As[la_k+2][la_m] = av.z; As[la_k+3][la_m] = av.w;
        *(float4*)&Bs[lb_k][lb_n] = bv4;
        __syncthreads();
        #pragma unroll
        for (int kk = 0; kk < 8; kk++) {
            float a[8], b[8];
            *(float4*)&a[0] = *(float4*)&As[kk][tr*8];
            *(float4*)&a[4] = *(float4*)&As[kk][tr*8+4];
            *(float4*)&b[0] = *(float4*)&Bs[kk][tc*8];
            *(float4*)&b[4] = *(float4*)&Bs[kk][tc*8+4];
            #pragma unroll
            for (int i = 0; i < 8; i++)
                #pragma unroll
                for (int j = 0; j < 8; j++)
                    acc[i][j] += a[i] * b[j];
        }
    }

    const float scaling = 0.17677669529663687f; /* 32^-0.5 */
    const int d0 = (n0 + tc*8) & 31;  // head-dim start for this thread's 8 cols
    #pragma unroll
    for (int i = 0; i < 8; i++) {
        int m  = m0 + tr*8 + i;
        int bi = m / LL, l = m % LL;
        float vals[8];
        #pragma unroll
        for (int j = 0; j < 8; j++) {
            int c = n0 + tc*8 + j;
            float v = acc[i][j] + bias[c];
            if (z == 1) v *= scaling;
            vals[j] = v;
        }
        if (z != 2) {
            // fused rotary: pairs (even d, odd d) within head
            float sv[8], cv[8];
            *(float4*)&sv[0] = *(const float4*)&sinv[l*HD + d0];
            *(float4*)&sv[4] = *(const float4*)&sinv[l*HD + d0 + 4];
            *(float4*)&cv[0] = *(const float4*)&cosv[l*HD + d0];
            *(float4*)&cv[4] = *(const float4*)&cosv[l*HD + d0 + 4];
            #pragma unroll
            for (int p = 0; p < 4; p++) {
                float e = vals[2*p], o = vals[2*p+1];
                vals[2*p]   = e*cv[2*p]   - o*sv[2*p];
                vals[2*p+1] = o*cv[2*p+1] + e*sv[2*p+1];
            }
        }
        #pragma unroll
        for (int j = 0; j < 8; j++) {
            int c = n0 + tc*8 + j;
            int n = c >> 5, d = c & 31;
            int idx = ((bi*NHEAD + n)*LL + l)*HD + d;
            if (z == 0)      g_q[idx] = vals[j];
            else if (z == 1) g_k[idx] = vals[j];
            else { g_vh[idx] = vals[j]; g_vn[(bi*LL + l)*CC + c] = vals[j]; }
        }
    }
}

// ---------------- 5x5 depthwise conv (LEPE) -----------------------------------
__global__ __launch_bounds__(256) void lepe_conv(const float* __restrict__ wdw,
                                                 const float* __restrict__ bdw)
{
    int c = threadIdx.x;
    int p = blockIdx.x;                 // 0..BB*LL-1
    int bi = p / LL; int l = p % LL;
    int h = l / WW, w = l % WW;
    float acc = bdw[c];
    #pragma unroll
    for (int dy = 0; dy < 5; dy++) {
        int hy = h + dy - 2;
        if (hy < 0 || hy >= HH) continue;
        #pragma unroll
        for (int dx = 0; dx < 5; dx++) {
            int wx = w + dx - 2;
            if (wx < 0 || wx >= WW) continue;
            acc += g_vn[(bi*LL + hy*WW + wx)*CC + c] * wdw[(dy*5+dx)*CC + c];
        }
    }
    g_lepe[p*CC + c] = acc;
}

// ---------------- flash attention via mma.sync tf32 ---------------------------
// CTA: (b, 128-row tile, head). 8 warps, 16 rows each. BC=64 keys per tile.

__device__ __forceinline__ void mma_tf32(float c[4], const unsigned a[4],
                                         unsigned b0, unsigned b1) {
    asm("mma.sync.aligned.m16n8k8.row.col.f32.tf32.tf32.f32 "
        "{%0,%1,%2,%3}, {%4,%5,%6,%7}, {%8,%9}, {%0,%1,%2,%3};"
        : "+f"(c[0]), "+f"(c[1]), "+f"(c[2]), "+f"(c[3])
        : "r"(a[0]), "r"(a[1]), "r"(a[2]), "r"(a[3]), "r"(b0), "r"(b1));
}

#define TF32_HI_MASK 0xFFFFE000u
__device__ __forceinline__ void hilo(float v, unsigned& hi, unsigned& lo) {
    unsigned u = __float_as_uint(v) & TF32_HI_MASK;
    hi = u;
    lo = __float_as_uint(v - __uint_as_float(u));
}

#define KSTR 36
#define PSTR 68

__global__ __launch_bounds__(256, 2) void attn_mma(const float* __restrict__ mask)
{
    extern __shared__ float smem[];
    float (*Ksh)[KSTR] = (float(*)[KSTR])smem;
    float (*Vsh)[KSTR] = (float(*)[KSTR])(smem + 64*KSTR);
    float (*Psh)[PSTR] = (float(*)[PSTR])(smem + 2*64*KSTR);

    const int bi = blockIdx.x;           // batch fastest -> mask L2 pairing
    const int l0 = blockIdx.y * 128;
    const int n  = blockIdx.z;
    const int t = threadIdx.x, lane = t & 31, warp = t >> 5;
    const int qr = lane >> 2, qq = lane & 3;

    const int bn = bi*NHEAD + n;
    const float* qg = g_q  + (size_t)bn*LL*HD;
    const float* kg = g_k  + (size_t)bn*LL*HD;
    const float* vg = g_vh + (size_t)bn*LL*HD;

    const int row0 = l0 + warp*16 + qr;  // this thread's rows: row0, row0+8
    const float* mr0 = mask + (size_t)n*LL*LL + (size_t)row0*LL;
    const float* mr1 = mr0 + (size_t)8*LL;

    // preload Q A-fragments (4 k-chunks of 8)
    unsigned qA[4][4];
    #pragma unroll
    for (int k = 0; k < 4; k++) {
        qA[k][0] = __float_as_uint(qg[(row0  )*HD + k*8 + qq    ]);
        qA[k][1] = __float_as_uint(qg[(row0+8)*HD + k*8 + qq    ]);
        qA[k][2] = __float_as_uint(qg[(row0  )*HD + k*8 + qq + 4]);
        qA[k][3] = __float_as_uint(qg[(row0+8)*HD + k*8 + qq + 4]);
    }

    float o[4][4];
    #pragma unroll
    for (int i = 0; i < 4; i++)
        #pragma unroll
        for (int j = 0; j < 4; j++) o[i][j] = 0.f;
    float rm0 = -1e30f, rm1 = -1e30f, sum0 = 0.f, sum1 = 0.f;

    const int pr = warp*16 + qr;

    for (int j0 = 0; j0 < LL; j0 += 64) {
        __syncthreads();
        #pragma unroll
        for (int u = 0; u < 2; u++) {
            int idx = t + u*256;
            int r = idx >> 3, c4 = (idx & 7) * 4;
            *(float4*)&Ksh[r][c4] = *(const float4*)&kg[(j0+r)*HD + c4];
            *(float4*)&Vsh[r][c4] = *(const float4*)&vg[(j0+r)*HD + c4];
        }
        __syncthreads();

        // ---- S = mask + Q K^T  (init C frags with mask, accumulate MMA) ----
        float s[8][4];
        #pragma unroll
        for (int jn = 0; jn < 8; jn++) {
            float2 m0v = *(const float2*)&mr0[j0 + jn*8 + 2*qq];
            float2 m1v = *(const float2*)&mr1[j0 + jn*8 + 2*qq];
            s[jn][0] = m0v.x; s[jn][1] = m0v.y;
            s[jn][2] = m1v.x; s[jn][3] = m1v.y;
        }
        #pragma unroll
        for (int k = 0; k < 4; k++) {
            #pragma unroll
            for (int jn = 0; jn < 8; jn++) {
                unsigned b0 = __float_as_uint(Ksh[jn*8 + qr][k*8 + qq    ]);
                unsigned b1 = __float_as_uint(Ksh[jn*8 + qr][k*8 + qq + 4]);
                mma_tf32(s[jn], qA[k], b0, b1);
            }
        }

        // ---- online softmax (rows warp-local; quad reduce over lane&3) ----
        float tm0 = -1e30f, tm1 = -1e30f;
        #pragma unroll
        for (int jn = 0; jn < 8; jn++) {
            tm0 = fmaxf(tm0, fmaxf(s[jn][0], s[jn][1]));
            tm1 = fmaxf(tm1, fmaxf(s[jn][2], s[jn][3]));
        }
        tm0 = fmaxf(tm0, __shfl_xor_sync(0xffffffffu, tm0, 1));
        tm0 = fmaxf(tm0, __shfl_xor_sync(0xffffffffu, tm0, 2));
        tm1 = fmaxf(tm1, __shfl_xor_sync(0xffffffffu, tm1, 1));
        tm1 = fmaxf(tm1, __shfl_xor_sync(0xffffffffu, tm1, 2));
        float nm0 = fmaxf(rm0, tm0), nm1 = fmaxf(rm1, tm1);
        float sc0 = __expf(rm0 - nm0), sc1 = __expf(rm1 - nm1);
        float ts0 = 0.f, ts1 = 0.f;
        #pragma unroll
        for (int jn = 0; jn < 8; jn++) {
            s[jn][0] = __expf(s[jn][0] - nm0);
            s[jn][1] = __expf(s[jn][1] - nm0);
            s[jn][2] = __expf(s[jn][2] - nm1);
            s[jn][3] = __expf(s[jn][3] - nm1);
            ts0 += s[jn][0] + s[jn][1];
            ts1 += s[jn][2] + s[jn][3];
        }
        ts0 += __shfl_xor_sync(0xffffffffu, ts0, 1);
        ts0 += __shfl_xor_sync(0xffffffffu, ts0, 2);
        ts1 += __shfl_xor_sync(0xffffffffu, ts1, 1);
        ts1 += __shfl_xor_sync(0xffffffffu, ts1, 2);
        sum0 = sum0*sc0 + ts0;  sum1 = sum1*sc1 + ts1;
        rm0 = nm0; rm1 = nm1;
        #pragma unroll
        for (int dn = 0; dn < 4; dn++) {
            o[dn][0] *= sc0; o[dn][1] *= sc0;
            o[dn][2] *= sc1; o[dn][3] *= sc1;
        }

        // ---- P -> shared (warp-local), fix fragment layout ----
        __syncwarp();
        #pragma unroll
        for (int jn = 0; jn < 8; jn++) {
            *(float2*)&Psh[pr    ][jn*8 + 2*qq] = make_float2(s[jn][0], s[jn][1]);
            *(float2*)&Psh[pr + 8][jn*8 + 2*qq] = make_float2(s[jn][2], s[jn][3]);
        }
        __syncwarp();

        // ---- O += P V  with tf32 hi/lo split (3 mmas, drop lo*lo) ----
        #pragma unroll
        for (int kk = 0; kk < 8; kk++) {
            float p0 = Psh[pr    ][kk*8 + qq    ];
            float p1 = Psh[pr + 8][kk*8 + qq    ];
            float p2 = Psh[pr    ][kk*8 + qq + 4];
            float p3 = Psh[pr + 8][kk*8 + qq + 4];
            unsigned ahi[4], alo[4];
            hilo(p0, ahi[0], alo[0]); hilo(p1, ahi[1], alo[1]);
            hilo(p2, ahi[2], alo[2]); hilo(p3, ahi[3], alo[3]);
            #pragma unroll
            for (int dn = 0; dn < 4; dn++) {
                float v0 = Vsh[kk*8 + qq    ][dn*8 + qr];
                float v1 = Vsh[kk*8 + qq + 4][dn*8 + qr];
                unsigned bh0, bl0, bh1, bl1;
                hilo(v0, bh0, bl0); hilo(v1, bh1, bl1);
                mma_tf32(o[dn], ahi, bh0, bh1);
                mma_tf32(o[dn], alo, bh0, bh1);
                mma_tf32(o[dn], ahi, bl0, bl1);
            }
        }
    }

    float inv0 = 1.f / sum0, inv1 = 1.f / sum1;
    float* og0 = g_attn + ((size_t)(bi*LL + row0    ))*CC + n*HD;
    float* og1 = g_attn + ((size_t)(bi*LL + row0 + 8))*CC + n*HD;
    #pragma unroll
    for (int dn = 0; dn < 4; dn++) {
        *(float2*)&og0[dn*8 + 2*qq] = make_float2(o[dn][0]*inv0, o[dn][1]*inv0);
        *(float2*)&og1[dn*8 + 2*qq] = make_float2(o[dn][2]*inv1, o[dn][3]*inv1);
    }
}

#define ATTN_SMEM ((2*64*KSTR + 128*PSTR) * 4)

// ---------------- output GEMM: (attn + lepe) @ wo + bo ------------------------
__global__ __launch_bounds__(256) void out_gemm(const float* __restrict__ wo,
                                                const float* __restrict__ bo,
                                                float* __restrict__ out)
{
    __shared__ __align__(16) float As[8][132];
    __shared__ __align__(16) float Bs[8][128];

    const int t  = threadIdx.x;
    const int m0 = blockIdx.y * 128;
    const int n0 = blockIdx.x * 128;
    const int tr = t >> 4, tc = t & 15;

    float acc[8][8];
    #pragma unroll
    for (int i = 0; i < 8; i++)
        #pragma unroll
        for (int j = 0; j < 8; j++) acc[i][j] = 0.f;

    const int la_m = t >> 1, la_k = (t & 1) * 4;
    const int lb_k = t >> 5, lb_n = (t & 31) * 4;

    for (int k0 = 0; k0 < CC; k0 += 8) {
        float4 a1 = *(const float4*)&g_attn[(m0 + la_m)*CC + k0 + la_k];
        float4 a2 = *(const float4*)&g_lepe[(m0 + la_m)*CC + k0 + la_k];
        float4 av = make_float4(a1.x+a2.x, a1.y+a2.y, a1.z+a2.z, a1.w+a2.w);
        float4 bv4 = *(const float4*)&wo[(k0 + lb_k)*CC + n0 + lb_n];
        __syncthreads();
        As[la_k+0][la_m] = av.x; As[la_k+1][la_m] = av.y;
        As[la_k+2][la_m] = av.z; As[la_k+3][la_m] = av.w;
        *(float4*)&Bs[lb_k][lb_n] = bv4;
        __syncthreads();
        #pragma unroll
        for (int kk = 0; kk < 8; kk++) {
            float a[8], b[8];
            *(float4*)&a[0] = *(float4*)&As[kk][tr*8];
            *(float4*)&a[4] = *(float4*)&As[kk][tr*8+4];
            *(float4*)&b[0] = *(float4*)&Bs[kk][tc*8];
            *(float4*)&b[4] = *(float4*)&Bs[kk][tc*8+4];
            #pragma unroll
            for (int i = 0; i < 8; i++)
                #pragma unroll
                for (int j = 0; j < 8; j++)
                    acc[i][j] += a[i] * b[j];
        }
    }

    #pragma unroll
    for (int i = 0; i < 8; i++) {
        int m = m0 + tr*8 + i;
        #pragma unroll
        for (int j = 0; j < 8; j += 4) {
            int c = n0 + tc*8 + j;
            float4 v;
            v.x = acc[i][j+0] + bo[c+0];
            v.y = acc[i][j+1] + bo[c+1];
            v.z = acc[i][j+2] + bo[c+2];
            v.w = acc[i][j+3] + bo[c+3];
            *(float4*)&out[m*CC + c] = v;
        }
    }
}

// ---------------- launch -------------------------------------------------------
extern "C" void kernel_launch(void* const* d_in, const int* in_sizes, int n_in,
                              void* d_out, int out_size)
{
    const float* x    = (const float*)d_in[0];
    const float* sinv = (const float*)d_in[1];
    const float* cosv = (const float*)d_in[2];
    const float* mask = (const float*)d_in[3];
    const float* wq   = (const float*)d_in[4];
    const float* bq   = (const float*)d_in[5];
    const float* wk   = (const float*)d_in[6];
    const float* bk   = (const float*)d_in[7];
    const float* wv   = (const float*)d_in[8];
    const float* bv   = (const float*)d_in[9];
    const float* wdw  = (const float*)d_in[10];
    const float* bdw  = (const float*)d_in[11];
    const float* wo   = (const float*)d_in[12];
    const float* bo   = (const float*)d_in[13];
    float* out = (float*)d_out;

    cudaFuncSetAttribute(attn_mma, cudaFuncAttributeMaxDynamicSharedMemorySize,
                         ATTN_SMEM);

    qkv_gemm<<<dim3(CC/128, MTOT/128, 3), 256>>>(x, wq, bq, wk, bk, wv, bv,
                                                 sinv, cosv);

    lepe_conv<<<BB*LL, 256>>>(wdw, bdw);

    attn_mma<<<dim3(BB, LL/128, NHEAD), 256, ATTN_SMEM>>>(mask);

    out_gemm<<<dim3(CC/128, MTOT/128), 256>>>(wo, bo, out);
}

// round 4
// speedup vs baseline: 3.4358x; 1.4300x over previous
#include <cuda_runtime.h>

#define BB    2
#define HH    48
#define WW    48
#define CC    256
#define NHEAD 8
#define HD    32
#define LL    (HH*WW)      /* 2304 */
#define MTOT  (BB*LL)      /* 4608 */

// ---------------- scratch (device globals; no allocs allowed) ----------------
__device__ float g_q   [BB*NHEAD*LL*HD];   // head-major [b][n][l][hd] (rotary applied)
__device__ float g_k   [BB*NHEAD*LL*HD];
__device__ float g_vh  [BB*NHEAD*LL*HD];   // V head-major
__device__ float g_vn  [BB*LL*CC];         // V in NHWC (for depthwise conv)
__device__ float g_lepe[BB*LL*CC];
__device__ float g_attn[BB*LL*CC];         // attention out, [b][l][c]

// ---------------- mma helpers --------------------------------------------------
__device__ __forceinline__ void mma_tf32(float c[4], const unsigned a[4],
                                         unsigned b0, unsigned b1) {
    asm("mma.sync.aligned.m16n8k8.row.col.f32.tf32.tf32.f32 "
        "{%0,%1,%2,%3}, {%4,%5,%6,%7}, {%8,%9}, {%0,%1,%2,%3};"
        : "+f"(c[0]), "+f"(c[1]), "+f"(c[2]), "+f"(c[3])
        : "r"(a[0]), "r"(a[1]), "r"(a[2]), "r"(a[3]), "r"(b0), "r"(b1));
}
#define TF32_HI_MASK 0xFFFFE000u
__device__ __forceinline__ void hilo(float v, unsigned& hi, unsigned& lo) {
    unsigned u = __float_as_uint(v) & TF32_HI_MASK;
    hi = u;
    lo = __float_as_uint(v - __uint_as_float(u));
}

// ---------------- tf32 MMA GEMM tiles: 64x128x(K=256), BK=32 -------------------
#define ASTR 36
#define BSTR 132

// QKV projection + bias + (rotary for q,k) + head-major scatter
__global__ __launch_bounds__(256) void qkv_mma(
    const float* __restrict__ x,
    const float* __restrict__ wq, const float* __restrict__ bq,
    const float* __restrict__ wk, const float* __restrict__ bk,
    const float* __restrict__ wv, const float* __restrict__ bv,
    const float* __restrict__ sinv, const float* __restrict__ cosv)
{
    const int z = blockIdx.z;
    const float* Wm   = (z == 0) ? wq : (z == 1) ? wk : wv;
    const float* bias = (z == 0) ? bq : (z == 1) ? bk : bv;

    __shared__ __align__(16) float As[64][ASTR];
    __shared__ __align__(16) float Bs[32][BSTR];

    const int t = threadIdx.x, lane = t & 31, warp = t >> 5;
    const int qr = lane >> 2, qq = lane & 3;
    const int wm = warp >> 2, wn = warp & 3;        // 2 x 4 warp grid
    const int m0 = blockIdx.y * 64;
    const int n0 = blockIdx.x * 128;

    // global load indices
    const int ar = t >> 3, ac = (t & 7) * 4;        // A: rows ar, ar+32
    const int bkr = warp, bnc = lane * 4;           // B: rows bkr, bkr+8.. (u*8)

    float acc[2][4][4];
    #pragma unroll
    for (int i = 0; i < 2; i++)
        #pragma unroll
        for (int j = 0; j < 4; j++)
            #pragma unroll
            for (int r = 0; r < 4; r++) acc[i][j][r] = 0.f;

    float4 aA, aB, b4[4];
    aA = *(const float4*)&x[(m0 + ar)*CC + ac];
    aB = *(const float4*)&x[(m0 + ar + 32)*CC + ac];
    #pragma unroll
    for (int u = 0; u < 4; u++)
        b4[u] = *(const float4*)&Wm[(bkr + u*8)*CC + n0 + bnc];

    for (int it = 0; it < 8; it++) {
        if (it) __syncthreads();
        *(float4*)&As[ar][ac]      = aA;
        *(float4*)&As[ar + 32][ac] = aB;
        #pragma unroll
        for (int u = 0; u < 4; u++)
            *(float4*)&Bs[bkr + u*8][bnc] = b4[u];
        __syncthreads();
        if (it < 7) {
            int k0 = (it + 1) * 32;
            aA = *(const float4*)&x[(m0 + ar)*CC + k0 + ac];
            aB = *(const float4*)&x[(m0 + ar + 32)*CC + k0 + ac];
            #pragma unroll
            for (int u = 0; u < 4; u++)
                b4[u] = *(const float4*)&Wm[(k0 + bkr + u*8)*CC + n0 + bnc];
        }
        #pragma unroll
        for (int kb = 0; kb < 4; kb++) {
            unsigned ahi[2][4], alo[2][4];
            #pragma unroll
            for (int mf = 0; mf < 2; mf++) {
                int arow = wm*32 + mf*16 + qr;
                float a0 = As[arow    ][kb*8 + qq];
                float a1 = As[arow + 8][kb*8 + qq];
                float a2 = As[arow    ][kb*8 + qq + 4];
                float a3 = As[arow + 8][kb*8 + qq + 4];
                hilo(a0, ahi[mf][0], alo[mf][0]);
                hilo(a1, ahi[mf][1], alo[mf][1]);
                hilo(a2, ahi[mf][2], alo[mf][2]);
                hilo(a3, ahi[mf][3], alo[mf][3]);
            }
            #pragma unroll
            for (int nf = 0; nf < 4; nf++) {
                int bcol = wn*32 + nf*8 + qr;
                float b0 = Bs[kb*8 + qq    ][bcol];
                float b1 = Bs[kb*8 + qq + 4][bcol];
                unsigned bh0, bl0, bh1, bl1;
                hilo(b0, bh0, bl0); hilo(b1, bh1, bl1);
                #pragma unroll
                for (int mf = 0; mf < 2; mf++) {
                    mma_tf32(acc[mf][nf], ahi[mf], bh0, bh1);
                    mma_tf32(acc[mf][nf], alo[mf], bh0, bh1);
                    mma_tf32(acc[mf][nf], ahi[mf], bl0, bl1);
                }
            }
        }
    }

    const float scaling = 0.17677669529663687f; /* 32^-0.5 */
    #pragma unroll
    for (int mf = 0; mf < 2; mf++) {
        #pragma unroll
        for (int nf = 0; nf < 4; nf++) {
            int cbase = n0 + wn*32 + nf*8 + 2*qq;
            int n = cbase >> 5, d = cbase & 31;
            #pragma unroll
            for (int rr = 0; rr < 2; rr++) {
                int m = m0 + wm*32 + mf*16 + qr + rr*8;
                int bi = m / LL, l = m - bi*LL;
                float e = acc[mf][nf][rr*2 + 0] + __ldg(&bias[cbase]);
                float o = acc[mf][nf][rr*2 + 1] + __ldg(&bias[cbase + 1]);
                if (z == 1) { e *= scaling; o *= scaling; }
                if (z != 2) {
                    float2 sv = *(const float2*)&sinv[l*HD + d];
                    float2 cv = *(const float2*)&cosv[l*HD + d];
                    float e2 = e*cv.x - o*sv.x;
                    float o2 = o*cv.y + e*sv.y;
                    e = e2; o = o2;
                }
                size_t idx = ((size_t)(bi*NHEAD + n)*LL + l)*HD + d;
                if (z == 0)      *(float2*)&g_q[idx] = make_float2(e, o);
                else if (z == 1) *(float2*)&g_k[idx] = make_float2(e, o);
                else {
                    *(float2*)&g_vh[idx] = make_float2(e, o);
                    *(float2*)&g_vn[((size_t)(bi*LL + l))*CC + cbase] =
                        make_float2(e, o);
                }
            }
        }
    }
}

// output projection: (attn + lepe) @ wo + bo
__global__ __launch_bounds__(256) void out_mma(const float* __restrict__ wo,
                                               const float* __restrict__ bo,
                                               float* __restrict__ out)
{
    __shared__ __align__(16) float As[64][ASTR];
    __shared__ __align__(16) float Bs[32][BSTR];

    const int t = threadIdx.x, lane = t & 31, warp = t >> 5;
    const int qr = lane >> 2, qq = lane & 3;
    const int wm = warp >> 2, wn = warp & 3;
    const int m0 = blockIdx.y * 64;
    const int n0 = blockIdx.x * 128;

    const int ar = t >> 3, ac = (t & 7) * 4;
    const int bkr = warp, bnc = lane * 4;

    float acc[2][4][4];
    #pragma unroll
    for (int i = 0; i < 2; i++)
        #pragma unroll
        for (int j = 0; j < 4; j++)
            #pragma unroll
            for (int r = 0; r < 4; r++) acc[i][j][r] = 0.f;

    float4 aA, aB, b4[4];
    {
        float4 u1 = *(const float4*)&g_attn[(m0 + ar)*CC + ac];
        float4 u2 = *(const float4*)&g_lepe[(m0 + ar)*CC + ac];
        aA = make_float4(u1.x+u2.x, u1.y+u2.y, u1.z+u2.z, u1.w+u2.w);
        float4 u3 = *(const float4*)&g_attn[(m0 + ar + 32)*CC + ac];
        float4 u4 = *(const float4*)&g_lepe[(m0 + ar + 32)*CC + ac];
        aB = make_float4(u3.x+u4.x, u3.y+u4.y, u3.z+u4.z, u3.w+u4.w);
    }
    #pragma unroll
    for (int u = 0; u < 4; u++)
        b4[u] = *(const float4*)&wo[(bkr + u*8)*CC + n0 + bnc];

    for (int it = 0; it < 8; it++) {
        if (it) __syncthreads();
        *(float4*)&As[ar][ac]      = aA;
        *(float4*)&As[ar + 32][ac] = aB;
        #pragma unroll
        for (int u = 0; u < 4; u++)
            *(float4*)&Bs[bkr + u*8][bnc] = b4[u];
        __syncthreads();
        if (it < 7) {
            int k0 = (it + 1) * 32;
            float4 u1 = *(const float4*)&g_attn[(m0 + ar)*CC + k0 + ac];
            float4 u2 = *(const float4*)&g_lepe[(m0 + ar)*CC + k0 + ac];
            aA = make_float4(u1.x+u2.x, u1.y+u2.y, u1.z+u2.z, u1.w+u2.w);
            float4 u3 = *(const float4*)&g_attn[(m0 + ar + 32)*CC + k0 + ac];
            float4 u4 = *(const float4*)&g_lepe[(m0 + ar + 32)*CC + k0 + ac];
            aB = make_float4(u3.x+u4.x, u3.y+u4.y, u3.z+u4.z, u3.w+u4.w);
            #pragma unroll
            for (int u = 0; u < 4; u++)
                b4[u] = *(const float4*)&wo[(k0 + bkr + u*8)*CC + n0 + bnc];
        }
        #pragma unroll
        for (int kb = 0; kb < 4; kb++) {
            unsigned ahi[2][4], alo[2][4];
            #pragma unroll
            for (int mf = 0; mf < 2; mf++) {
                int arow = wm*32 + mf*16 + qr;
                float a0 = As[arow    ][kb*8 + qq];
                float a1 = As[arow + 8][kb*8 + qq];
                float a2 = As[arow    ][kb*8 + qq + 4];
                float a3 = As[arow + 8][kb*8 + qq + 4];
                hilo(a0, ahi[mf][0], alo[mf][0]);
                hilo(a1, ahi[mf][1], alo[mf][1]);
                hilo(a2, ahi[mf][2], alo[mf][2]);
                hilo(a3, ahi[mf][3], alo[mf][3]);
            }
            #pragma unroll
            for (int nf = 0; nf < 4; nf++) {
                int bcol = wn*32 + nf*8 + qr;
                float b0 = Bs[kb*8 + qq    ][bcol];
                float b1 = Bs[kb*8 + qq + 4][bcol];
                unsigned bh0, bl0, bh1, bl1;
                hilo(b0, bh0, bl0); hilo(b1, bh1, bl1);
                #pragma unroll
                for (int mf = 0; mf < 2; mf++) {
                    mma_tf32(acc[mf][nf], ahi[mf], bh0, bh1);
                    mma_tf32(acc[mf][nf], alo[mf], bh0, bh1);
                    mma_tf32(acc[mf][nf], ahi[mf], bl0, bl1);
                }
            }
        }
    }

    #pragma unroll
    for (int mf = 0; mf < 2; mf++) {
        #pragma unroll
        for (int nf = 0; nf < 4; nf++) {
            int cbase = n0 + wn*32 + nf*8 + 2*qq;
            float bx = __ldg(&bo[cbase]), by = __ldg(&bo[cbase + 1]);
            #pragma unroll
            for (int rr = 0; rr < 2; rr++) {
                int m = m0 + wm*32 + mf*16 + qr + rr*8;
                *(float2*)&out[(size_t)m*CC + cbase] =
                    make_float2(acc[mf][nf][rr*2] + bx,
                                acc[mf][nf][rr*2 + 1] + by);
            }
        }
    }
}

// ---------------- 5x5 depthwise conv (LEPE) -----------------------------------
__global__ __launch_bounds__(256) void lepe_conv(const float* __restrict__ wdw,
                                                 const float* __restrict__ bdw)
{
    int c = threadIdx.x;
    int p = blockIdx.x;                 // 0..BB*LL-1
    int bi = p / LL; int l = p % LL;
    int h = l / WW, w = l % WW;
    float acc = bdw[c];
    #pragma unroll
    for (int dy = 0; dy < 5; dy++) {
        int hy = h + dy - 2;
        if (hy < 0 || hy >= HH) continue;
        #pragma unroll
        for (int dx = 0; dx < 5; dx++) {
            int wx = w + dx - 2;
            if (wx < 0 || wx >= WW) continue;
            acc += g_vn[(bi*LL + hy*WW + wx)*CC + c] * wdw[(dy*5+dx)*CC + c];
        }
    }
    g_lepe[p*CC + c] = acc;
}

// ---------------- flash attention via mma.sync tf32 ---------------------------
#define KSTR 36
#define PSTR 68

__global__ __launch_bounds__(256, 2) void attn_mma(const float* __restrict__ mask)
{
    extern __shared__ float smem[];
    float (*Ksh)[KSTR] = (float(*)[KSTR])smem;
    float (*Vsh)[KSTR] = (float(*)[KSTR])(smem + 64*KSTR);
    float (*Psh)[PSTR] = (float(*)[PSTR])(smem + 2*64*KSTR);

    const int bi = blockIdx.x;           // batch fastest -> mask L2 pairing
    const int l0 = blockIdx.y * 128;
    const int n  = blockIdx.z;
    const int t = threadIdx.x, lane = t & 31, warp = t >> 5;
    const int qr = lane >> 2, qq = lane & 3;

    const int bn = bi*NHEAD + n;
    const float* qg = g_q  + (size_t)bn*LL*HD;
    const float* kg = g_k  + (size_t)bn*LL*HD;
    const float* vg = g_vh + (size_t)bn*LL*HD;

    const int row0 = l0 + warp*16 + qr;  // this thread's rows: row0, row0+8
    const float* mr0 = mask + (size_t)n*LL*LL + (size_t)row0*LL;
    const float* mr1 = mr0 + (size_t)8*LL;

    // preload Q A-fragments (4 k-chunks of 8)
    unsigned qA[4][4];
    #pragma unroll
    for (int k = 0; k < 4; k++) {
        qA[k][0] = __float_as_uint(qg[(row0  )*HD + k*8 + qq    ]);
        qA[k][1] = __float_as_uint(qg[(row0+8)*HD + k*8 + qq    ]);
        qA[k][2] = __float_as_uint(qg[(row0  )*HD + k*8 + qq + 4]);
        qA[k][3] = __float_as_uint(qg[(row0+8)*HD + k*8 + qq + 4]);
    }

    float o[4][4];
    #pragma unroll
    for (int i = 0; i < 4; i++)
        #pragma unroll
        for (int j = 0; j < 4; j++) o[i][j] = 0.f;
    float rm0 = -1e30f, rm1 = -1e30f, sum0 = 0.f, sum1 = 0.f;

    const int pr = warp*16 + qr;
    const int lr = t >> 3;             // 0..31
    const int lc = (t & 7) * 4;        // 0..28

    // prefetch tile 0 into registers
    float4 kA = *(const float4*)&kg[(lr     )*HD + lc];
    float4 kB = *(const float4*)&kg[(lr + 32)*HD + lc];
    float4 vA = *(const float4*)&vg[(lr     )*HD + lc];
    float4 vB = *(const float4*)&vg[(lr + 32)*HD + lc];

    for (int j0 = 0; j0 < LL; j0 += 64) {
        __syncthreads();
        *(float4*)&Ksh[lr     ][lc] = kA;
        *(float4*)&Ksh[lr + 32][lc] = kB;
        *(float4*)&Vsh[lr     ][lc] = vA;
        *(float4*)&Vsh[lr + 32][lc] = vB;
        __syncthreads();
        if (j0 + 64 < LL) {
            const float* kn = kg + (size_t)(j0 + 64)*HD;
            const float* vn = vg + (size_t)(j0 + 64)*HD;
            kA = *(const float4*)&kn[(lr     )*HD + lc];
            kB = *(const float4*)&kn[(lr + 32)*HD + lc];
            vA = *(const float4*)&vn[(lr     )*HD + lc];
            vB = *(const float4*)&vn[(lr + 32)*HD + lc];
        }

        // ---- S = mask + Q K^T ----
        float s[8][4];
        #pragma unroll
        for (int jn = 0; jn < 8; jn++) {
            float2 m0v = *(const float2*)&mr0[j0 + jn*8 + 2*qq];
            float2 m1v = *(const float2*)&mr1[j0 + jn*8 + 2*qq];
            s[jn][0] = m0v.x; s[jn][1] = m0v.y;
            s[jn][2] = m1v.x; s[jn][3] = m1v.y;
        }
        #pragma unroll
        for (int k = 0; k < 4; k++) {
            #pragma unroll
            for (int jn = 0; jn < 8; jn++) {
                unsigned b0 = __float_as_uint(Ksh[jn*8 + qr][k*8 + qq    ]);
                unsigned b1 = __float_as_uint(Ksh[jn*8 + qr][k*8 + qq + 4]);
                mma_tf32(s[jn], qA[k], b0, b1);
            }
        }

        // ---- online softmax ----
        float tm0 = -1e30f, tm1 = -1e30f;
        #pragma unroll
        for (int jn = 0; jn < 8; jn++) {
            tm0 = fmaxf(tm0, fmaxf(s[jn][0], s[jn][1]));
            tm1 = fmaxf(tm1, fmaxf(s[jn][2], s[jn][3]));
        }
        tm0 = fmaxf(tm0, __shfl_xor_sync(0xffffffffu, tm0, 1));
        tm0 = fmaxf(tm0, __shfl_xor_sync(0xffffffffu, tm0, 2));
        tm1 = fmaxf(tm1, __shfl_xor_sync(0xffffffffu, tm1, 1));
        tm1 = fmaxf(tm1, __shfl_xor_sync(0xffffffffu, tm1, 2));
        float nm0 = fmaxf(rm0, tm0), nm1 = fmaxf(rm1, tm1);
        float sc0 = __expf(rm0 - nm0), sc1 = __expf(rm1 - nm1);
        float ts0 = 0.f, ts1 = 0.f;
        #pragma unroll
        for (int jn = 0; jn < 8; jn++) {
            s[jn][0] = __expf(s[jn][0] - nm0);
            s[jn][1] = __expf(s[jn][1] - nm0);
            s[jn][2] = __expf(s[jn][2] - nm1);
            s[jn][3] = __expf(s[jn][3] - nm1);
            ts0 += s[jn][0] + s[jn][1];
            ts1 += s[jn][2] + s[jn][3];
        }
        ts0 += __shfl_xor_sync(0xffffffffu, ts0, 1);
        ts0 += __shfl_xor_sync(0xffffffffu, ts0, 2);
        ts1 += __shfl_xor_sync(0xffffffffu, ts1, 1);
        ts1 += __shfl_xor_sync(0xffffffffu, ts1, 2);
        sum0 = sum0*sc0 + ts0;  sum1 = sum1*sc1 + ts1;
        rm0 = nm0; rm1 = nm1;
        #pragma unroll
        for (int dn = 0; dn < 4; dn++) {
            o[dn][0] *= sc0; o[dn][1] *= sc0;
            o[dn][2] *= sc1; o[dn][3] *= sc1;
        }

        // ---- P -> shared (warp-local), fix fragment layout ----
        __syncwarp();
        #pragma unroll
        for (int jn = 0; jn < 8; jn++) {
            *(float2*)&Psh[pr    ][jn*8 + 2*qq] = make_float2(s[jn][0], s[jn][1]);
            *(float2*)&Psh[pr + 8][jn*8 + 2*qq] = make_float2(s[jn][2], s[jn][3]);
        }
        __syncwarp();

        // ---- O += P V : P hi/lo split (2 mmas), V raw tf32 ----
        #pragma unroll
        for (int kk = 0; kk < 8; kk++) {
            float p0 = Psh[pr    ][kk*8 + qq    ];
            float p1 = Psh[pr + 8][kk*8 + qq    ];
            float p2 = Psh[pr    ][kk*8 + qq + 4];
            float p3 = Psh[pr + 8][kk*8 + qq + 4];
            unsigned ahi[4], alo[4];
            hilo(p0, ahi[0], alo[0]); hilo(p1, ahi[1], alo[1]);
            hilo(p2, ahi[2], alo[2]); hilo(p3, ahi[3], alo[3]);
            #pragma unroll
            for (int dn = 0; dn < 4; dn++) {
                unsigned b0 = __float_as_uint(Vsh[kk*8 + qq    ][dn*8 + qr]);
                unsigned b1 = __float_as_uint(Vsh[kk*8 + qq + 4][dn*8 + qr]);
                mma_tf32(o[dn], ahi, b0, b1);
                mma_tf32(o[dn], alo, b0, b1);
            }
        }
    }

    float inv0 = 1.f / sum0, inv1 = 1.f / sum1;
    float* og0 = g_attn + ((size_t)(bi*LL + row0    ))*CC + n*HD;
    float* og1 = g_attn + ((size_t)(bi*LL + row0 + 8))*CC + n*HD;
    #pragma unroll
    for (int dn = 0; dn < 4; dn++) {
        *(float2*)&og0[dn*8 + 2*qq] = make_float2(o[dn][0]*inv0, o[dn][1]*inv0);
        *(float2*)&og1[dn*8 + 2*qq] = make_float2(o[dn][2]*inv1, o[dn][3]*inv1);
    }
}

#define ATTN_SMEM ((2*64*KSTR + 128*PSTR) * 4)

// ---------------- launch -------------------------------------------------------
extern "C" void kernel_launch(void* const* d_in, const int* in_sizes, int n_in,
                              void* d_out, int out_size)
{
    const float* x    = (const float*)d_in[0];
    const float* sinv = (const float*)d_in[1];
    const float* cosv = (const float*)d_in[2];
    const float* mask = (const float*)d_in[3];
    const float* wq   = (const float*)d_in[4];
    const float* bq   = (const float*)d_in[5];
    const float* wk   = (const float*)d_in[6];
    const float* bk   = (const float*)d_in[7];
    const float* wv   = (const float*)d_in[8];
    const float* bv   = (const float*)d_in[9];
    const float* wdw  = (const float*)d_in[10];
    const float* bdw  = (const float*)d_in[11];
    const float* wo   = (const float*)d_in[12];
    const float* bo   = (const float*)d_in[13];
    float* out = (float*)d_out;

    cudaFuncSetAttribute(attn_mma, cudaFuncAttributeMaxDynamicSharedMemorySize,
                         ATTN_SMEM);

    qkv_mma<<<dim3(CC/128, MTOT/64, 3), 256>>>(x, wq, bq, wk, bk, wv, bv,
                                               sinv, cosv);

    lepe_conv<<<BB*LL, 256>>>(wdw, bdw);

    attn_mma<<<dim3(BB, LL/128, NHEAD), 256, ATTN_SMEM>>>(mask);

    out_mma<<<dim3(CC/128, MTOT/64), 256>>>(wo, bo, out);
}

// round 6
// speedup vs baseline: 3.5210x; 1.0248x over previous
#include <cuda_runtime.h>

#define BB    2
#define HH    48
#define WW    48
#define CC    256
#define NHEAD 8
#define HD    32
#define LL    (HH*WW)      /* 2304 */
#define MTOT  (BB*LL)      /* 4608 */

// ---------------- scratch (device globals; no allocs allowed) ----------------
__device__ float g_q   [BB*NHEAD*LL*HD];   // head-major [b][n][l][hd] (rotary applied)
__device__ float g_k   [BB*NHEAD*LL*HD];
__device__ float g_vh  [BB*NHEAD*LL*HD];   // V head-major
__device__ float g_vn  [BB*LL*CC];         // V in NHWC (for depthwise conv)
__device__ float g_lepe[BB*LL*CC];
__device__ float g_attn[BB*LL*CC];         // attention out, [b][l][c]

// ---------------- mma helpers --------------------------------------------------
__device__ __forceinline__ void mma_tf32(float c[4], const unsigned a[4],
                                         unsigned b0, unsigned b1) {
    asm("mma.sync.aligned.m16n8k8.row.col.f32.tf32.tf32.f32 "
        "{%0,%1,%2,%3}, {%4,%5,%6,%7}, {%8,%9}, {%0,%1,%2,%3};"
        : "+f"(c[0]), "+f"(c[1]), "+f"(c[2]), "+f"(c[3])
        : "r"(a[0]), "r"(a[1]), "r"(a[2]), "r"(a[3]), "r"(b0), "r"(b1));
}
#define TF32_HI_MASK 0xFFFFE000u
__device__ __forceinline__ void hilo(float v, unsigned& hi, unsigned& lo) {
    unsigned u = __float_as_uint(v) & TF32_HI_MASK;
    hi = u;
    lo = __float_as_uint(v - __uint_as_float(u));
}

// ---------------- tf32 MMA GEMM tiles: 64x128x(K=256), BK=32 -------------------
#define ASTR 36
#define BSTR 132
#define AS_SZ (64*ASTR)
#define BS_SZ (32*BSTR)
#define GEMM_SMEM ((2*AS_SZ + 2*BS_SZ) * 4)

// QKV projection + bias + (rotary for q,k) + head-major scatter
__global__ __launch_bounds__(256) void qkv_mma(
    const float* __restrict__ x,
    const float* __restrict__ wq, const float* __restrict__ bq,
    const float* __restrict__ wk, const float* __restrict__ bk,
    const float* __restrict__ wv, const float* __restrict__ bv,
    const float* __restrict__ sinv, const float* __restrict__ cosv)
{
    const int z = blockIdx.z;
    const float* Wm   = (z == 0) ? wq : (z == 1) ? wk : wv;
    const float* bias = (z == 0) ? bq : (z == 1) ? bk : bv;

    extern __shared__ float sm[];
    float* AsB[2] = { sm, sm + AS_SZ };
    float* BsB[2] = { sm + 2*AS_SZ, sm + 2*AS_SZ + BS_SZ };

    const int t = threadIdx.x, lane = t & 31, warp = t >> 5;
    const int qr = lane >> 2, qq = lane & 3;
    const int wm = warp >> 2, wn = warp & 3;        // 2 x 4 warp grid
    const int m0 = blockIdx.y * 64;
    const int n0 = blockIdx.x * 128;

    const int ar = t >> 3, ac = (t & 7) * 4;        // A: rows ar, ar+32
    const int bkr = warp, bnc = lane * 4;           // B: rows bkr + u*8

    float acc[2][4][4];
    #pragma unroll
    for (int i = 0; i < 2; i++)
        #pragma unroll
        for (int j = 0; j < 4; j++)
            #pragma unroll
            for (int r = 0; r < 4; r++) acc[i][j][r] = 0.f;

    float4 aA, aB, b4[4];
    aA = *(const float4*)&x[(m0 + ar)*CC + ac];
    aB = *(const float4*)&x[(m0 + ar + 32)*CC + ac];
    #pragma unroll
    for (int u = 0; u < 4; u++)
        b4[u] = *(const float4*)&Wm[(bkr + u*8)*CC + n0 + bnc];
    *(float4*)&AsB[0][ar*ASTR + ac]        = aA;
    *(float4*)&AsB[0][(ar + 32)*ASTR + ac] = aB;
    #pragma unroll
    for (int u = 0; u < 4; u++)
        *(float4*)&BsB[0][(bkr + u*8)*BSTR + bnc] = b4[u];
    __syncthreads();

    for (int it = 0; it < 8; it++) {
        const float* As = AsB[it & 1];
        const float* Bs = BsB[it & 1];
        if (it < 7) {
            int k0 = (it + 1) * 32;
            aA = *(const float4*)&x[(m0 + ar)*CC + k0 + ac];
            aB = *(const float4*)&x[(m0 + ar + 32)*CC + k0 + ac];
            #pragma unroll
            for (int u = 0; u < 4; u++)
                b4[u] = *(const float4*)&Wm[(k0 + bkr + u*8)*CC + n0 + bnc];
        }
        #pragma unroll
        for (int kb = 0; kb < 4; kb++) {
            unsigned ahi[2][4], alo[2][4];
            #pragma unroll
            for (int mf = 0; mf < 2; mf++) {
                int arow = wm*32 + mf*16 + qr;
                float a0 = As[arow*ASTR + kb*8 + qq];
                float a1 = As[(arow + 8)*ASTR + kb*8 + qq];
                float a2 = As[arow*ASTR + kb*8 + qq + 4];
                float a3 = As[(arow + 8)*ASTR + kb*8 + qq + 4];
                hilo(a0, ahi[mf][0], alo[mf][0]);
                hilo(a1, ahi[mf][1], alo[mf][1]);
                hilo(a2, ahi[mf][2], alo[mf][2]);
                hilo(a3, ahi[mf][3], alo[mf][3]);
            }
            #pragma unroll
            for (int nf = 0; nf < 4; nf++) {
                int bcol = wn*32 + nf*8 + qr;
                float b0 = Bs[(kb*8 + qq)*BSTR + bcol];
                float b1 = Bs[(kb*8 + qq + 4)*BSTR + bcol];
                unsigned bh0, bl0, bh1, bl1;
                hilo(b0, bh0, bl0); hilo(b1, bh1, bl1);
                #pragma unroll
                for (int mf = 0; mf < 2; mf++) {
                    mma_tf32(acc[mf][nf], ahi[mf], bh0, bh1);
                    mma_tf32(acc[mf][nf], alo[mf], bh0, bh1);
                    mma_tf32(acc[mf][nf], ahi[mf], bl0, bl1);
                }
            }
        }
        if (it < 7) {
            float* An = AsB[(it + 1) & 1];
            float* Bn = BsB[(it + 1) & 1];
            *(float4*)&An[ar*ASTR + ac]        = aA;
            *(float4*)&An[(ar + 32)*ASTR + ac] = aB;
            #pragma unroll
            for (int u = 0; u < 4; u++)
                *(float4*)&Bn[(bkr + u*8)*BSTR + bnc] = b4[u];
            __syncthreads();
        }
    }

    const float scaling = 0.17677669529663687f; /* 32^-0.5 */
    #pragma unroll
    for (int mf = 0; mf < 2; mf++) {
        #pragma unroll
        for (int nf = 0; nf < 4; nf++) {
            int cbase = n0 + wn*32 + nf*8 + 2*qq;
            int n = cbase >> 5, d = cbase & 31;
            #pragma unroll
            for (int rr = 0; rr < 2; rr++) {
                int m = m0 + wm*32 + mf*16 + qr + rr*8;
                int bi = m / LL, l = m - bi*LL;
                float e = acc[mf][nf][rr*2 + 0] + __ldg(&bias[cbase]);
                float o = acc[mf][nf][rr*2 + 1] + __ldg(&bias[cbase + 1]);
                if (z == 1) { e *= scaling; o *= scaling; }
                if (z != 2) {
                    float2 sv = *(const float2*)&sinv[l*HD + d];
                    float2 cv = *(const float2*)&cosv[l*HD + d];
                    float e2 = e*cv.x - o*sv.x;
                    float o2 = o*cv.y + e*sv.y;
                    e = e2; o = o2;
                }
                size_t idx = ((size_t)(bi*NHEAD + n)*LL + l)*HD + d;
                if (z == 0)      *(float2*)&g_q[idx] = make_float2(e, o);
                else if (z == 1) *(float2*)&g_k[idx] = make_float2(e, o);
                else {
                    *(float2*)&g_vh[idx] = make_float2(e, o);
                    *(float2*)&g_vn[((size_t)(bi*LL + l))*CC + cbase] =
                        make_float2(e, o);
                }
            }
        }
    }
}

// output projection: (attn + lepe) @ wo + bo
__global__ __launch_bounds__(256) void out_mma(const float* __restrict__ wo,
                                               const float* __restrict__ bo,
                                               float* __restrict__ out)
{
    extern __shared__ float sm[];
    float* AsB[2] = { sm, sm + AS_SZ };
    float* BsB[2] = { sm + 2*AS_SZ, sm + 2*AS_SZ + BS_SZ };

    const int t = threadIdx.x, lane = t & 31, warp = t >> 5;
    const int qr = lane >> 2, qq = lane & 3;
    const int wm = warp >> 2, wn = warp & 3;
    const int m0 = blockIdx.y * 64;
    const int n0 = blockIdx.x * 128;

    const int ar = t >> 3, ac = (t & 7) * 4;
    const int bkr = warp, bnc = lane * 4;

    float acc[2][4][4];
    #pragma unroll
    for (int i = 0; i < 2; i++)
        #pragma unroll
        for (int j = 0; j < 4; j++)
            #pragma unroll
            for (int r = 0; r < 4; r++) acc[i][j][r] = 0.f;

    float4 aA, aB, b4[4];
    {
        float4 u1 = *(const float4*)&g_attn[(m0 + ar)*CC + ac];
        float4 u2 = *(const float4*)&g_lepe[(m0 + ar)*CC + ac];
        aA = make_float4(u1.x+u2.x, u1.y+u2.y, u1.z+u2.z, u1.w+u2.w);
        float4 u3 = *(const float4*)&g_attn[(m0 + ar + 32)*CC + ac];
        float4 u4 = *(const float4*)&g_lepe[(m0 + ar + 32)*CC + ac];
        aB = make_float4(u3.x+u4.x, u3.y+u4.y, u3.z+u4.z, u3.w+u4.w);
    }
    #pragma unroll
    for (int u = 0; u < 4; u++)
        b4[u] = *(const float4*)&wo[(bkr + u*8)*CC + n0 + bnc];
    *(float4*)&AsB[0][ar*ASTR + ac]        = aA;
    *(float4*)&AsB[0][(ar + 32)*ASTR + ac] = aB;
    #pragma unroll
    for (int u = 0; u < 4; u++)
        *(float4*)&BsB[0][(bkr + u*8)*BSTR + bnc] = b4[u];
    __syncthreads();

    for (int it = 0; it < 8; it++) {
        const float* As = AsB[it & 1];
        const float* Bs = BsB[it & 1];
        if (it < 7) {
            int k0 = (it + 1) * 32;
            float4 u1 = *(const float4*)&g_attn[(m0 + ar)*CC + k0 + ac];
            float4 u2 = *(const float4*)&g_lepe[(m0 + ar)*CC + k0 + ac];
            aA = make_float4(u1.x+u2.x, u1.y+u2.y, u1.z+u2.z, u1.w+u2.w);
            float4 u3 = *(const float4*)&g_attn[(m0 + ar + 32)*CC + k0 + ac];
            float4 u4 = *(const float4*)&g_lepe[(m0 + ar + 32)*CC + k0 + ac];
            aB = make_float4(u3.x+u4.x, u3.y+u4.y, u3.z+u4.z, u3.w+u4.w);
            #pragma unroll
            for (int u = 0; u < 4; u++)
                b4[u] = *(const float4*)&wo[(k0 + bkr + u*8)*CC + n0 + bnc];
        }
        #pragma unroll
        for (int kb = 0; kb < 4; kb++) {
            unsigned ahi[2][4], alo[2][4];
            #pragma unroll
            for (int mf = 0; mf < 2; mf++) {
                int arow = wm*32 + mf*16 + qr;
                float a0 = As[arow*ASTR + kb*8 + qq];
                float a1 = As[(arow + 8)*ASTR + kb*8 + qq];
                float a2 = As[arow*ASTR + kb*8 + qq + 4];
                float a3 = As[(arow + 8)*ASTR + kb*8 + qq + 4];
                hilo(a0, ahi[mf][0], alo[mf][0]);
                hilo(a1, ahi[mf][1], alo[mf][1]);
                hilo(a2, ahi[mf][2], alo[mf][2]);
                hilo(a3, ahi[mf][3], alo[mf][3]);
            }
            #pragma unroll
            for (int nf = 0; nf < 4; nf++) {
                int bcol = wn*32 + nf*8 + qr;
                float b0 = Bs[(kb*8 + qq)*BSTR + bcol];
                float b1 = Bs[(kb*8 + qq + 4)*BSTR + bcol];
                unsigned bh0, bl0, bh1, bl1;
                hilo(b0, bh0, bl0); hilo(b1, bh1, bl1);
                #pragma unroll
                for (int mf = 0; mf < 2; mf++) {
                    mma_tf32(acc[mf][nf], ahi[mf], bh0, bh1);
                    mma_tf32(acc[mf][nf], alo[mf], bh0, bh1);
                    mma_tf32(acc[mf][nf], ahi[mf], bl0, bl1);
                }
            }
        }
        if (it < 7) {
            float* An = AsB[(it + 1) & 1];
            float* Bn = BsB[(it + 1) & 1];
            *(float4*)&An[ar*ASTR + ac]        = aA;
            *(float4*)&An[(ar + 32)*ASTR + ac] = aB;
            #pragma unroll
            for (int u = 0; u < 4; u++)
                *(float4*)&Bn[(bkr + u*8)*BSTR + bnc] = b4[u];
            __syncthreads();
        }
    }

    #pragma unroll
    for (int mf = 0; mf < 2; mf++) {
        #pragma unroll
        for (int nf = 0; nf < 4; nf++) {
            int cbase = n0 + wn*32 + nf*8 + 2*qq;
            float bx = __ldg(&bo[cbase]), by = __ldg(&bo[cbase + 1]);
            #pragma unroll
            for (int rr = 0; rr < 2; rr++) {
                int m = m0 + wm*32 + mf*16 + qr + rr*8;
                *(float2*)&out[(size_t)m*CC + cbase] =
                    make_float2(acc[mf][nf][rr*2] + bx,
                                acc[mf][nf][rr*2 + 1] + by);
            }
        }
    }
}

// ---------------- 5x5 depthwise conv (LEPE), smem-tiled ------------------------
// grid: (36 pixel tiles of 8x8, 4 channel groups of 64, BB). block 256.
__global__ __launch_bounds__(256) void lepe_tiled(const float* __restrict__ wdw,
                                                  const float* __restrict__ bdw)
{
    __shared__ float patch[12*12*64];      // 36 KB

    const int t  = threadIdx.x;
    const int tx = blockIdx.x % 6, ty = blockIdx.x / 6;
    const int cg = blockIdx.y;             // channel group (64)
    const int bi = blockIdx.z;
    const int h0 = ty*8, w0 = tx*8;
    const int c0 = cg*64;

    // load 12x12 halo patch, 64 channels, zero-filled OOB
    #pragma unroll
    for (int i = 0; i < 9; i++) {
        int fidx = t + i*256;              // float4 index, 2304 total
        int c4  = (fidx & 15) * 4;
        int pix = fidx >> 4;               // 0..143
        int py = pix / 12, px = pix % 12;
        int hy = h0 + py - 2, wx = w0 + px - 2;
        float4 v = make_float4(0.f, 0.f, 0.f, 0.f);
        if (hy >= 0 && hy < HH && wx >= 0 && wx < WW)
            v = *(const float4*)&g_vn[((size_t)(bi*LL + hy*WW + wx))*CC + c0 + c4];
        *(float4*)&patch[(py*12 + px)*64 + c4] = v;
    }

    // weights for this thread's channel -> registers
    const int c  = t & 63;
    const int pg = t >> 6;                 // 0..3, 16 pixels each
    float wr[25];
    #pragma unroll
    for (int i = 0; i < 25; i++) wr[i] = __ldg(&wdw[i*CC + c0 + c]);
    const float bias = __ldg(&bdw[c0 + c]);

    __syncthreads();

    #pragma unroll
    for (int j = 0; j < 16; j++) {
        int pid = pg*16 + j;               // 0..63
        int py = pid >> 3, px = pid & 7;
        float acc = bias;
        #pragma unroll
        for (int dy = 0; dy < 5; dy++)
            #pragma unroll
            for (int dx = 0; dx < 5; dx++)
                acc += patch[((py+dy)*12 + (px+dx))*64 + c] * wr[dy*5+dx];
        g_lepe[((size_t)(bi*LL + (h0+py)*WW + (w0+px)))*CC + c0 + c] = acc;
    }
}

// ---------------- flash attention via mma.sync tf32 ---------------------------
#define KSTR 36
#define PSTR 68

__global__ __launch_bounds__(256, 2) void attn_mma(const float* __restrict__ mask)
{
    extern __shared__ float smem[];
    float (*Ksh)[KSTR] = (float(*)[KSTR])smem;
    float (*Vsh)[KSTR] = (float(*)[KSTR])(smem + 64*KSTR);
    float (*Psh)[PSTR] = (float(*)[PSTR])(smem + 2*64*KSTR);

    const int bi = blockIdx.x;           // batch fastest -> mask L2 pairing
    const int l0 = blockIdx.y * 128;
    const int n  = blockIdx.z;
    const int t = threadIdx.x, lane = t & 31, warp = t >> 5;
    const int qr = lane >> 2, qq = lane & 3;

    const int bn = bi*NHEAD + n;
    const float* qg = g_q  + (size_t)bn*LL*HD;
    const float* kg = g_k  + (size_t)bn*LL*HD;
    const float* vg = g_vh + (size_t)bn*LL*HD;

    const int row0 = l0 + warp*16 + qr;  // this thread's rows: row0, row0+8
    const float* mr0 = mask + (size_t)n*LL*LL + (size_t)row0*LL;
    const float* mr1 = mr0 + (size_t)8*LL;

    // preload Q A-fragments (4 k-chunks of 8)
    unsigned qA[4][4];
    #pragma unroll
    for (int k = 0; k < 4; k++) {
        qA[k][0] = __float_as_uint(qg[(row0  )*HD + k*8 + qq    ]);
        qA[k][1] = __float_as_uint(qg[(row0+8)*HD + k*8 + qq    ]);
        qA[k][2] = __float_as_uint(qg[(row0  )*HD + k*8 + qq + 4]);
        qA[k][3] = __float_as_uint(qg[(row0+8)*HD + k*8 + qq + 4]);
    }

    float o[4][4];
    #pragma unroll
    for (int i = 0; i < 4; i++)
        #pragma unroll
        for (int j = 0; j < 4; j++) o[i][j] = 0.f;
    float rm0 = -1e30f, rm1 = -1e30f, sum0 = 0.f, sum1 = 0.f;

    const int pr = warp*16 + qr;
    const int lr = t >> 3;             // 0..31
    const int lc = (t & 7) * 4;        // 0..28

    // prefetch tile 0 into registers
    float4 kA = *(const float4*)&kg[(lr     )*HD + lc];
    float4 kB = *(const float4*)&kg[(lr + 32)*HD + lc];
    float4 vA = *(const float4*)&vg[(lr     )*HD + lc];
    float4 vB = *(const float4*)&vg[(lr + 32)*HD + lc];

    for (int j0 = 0; j0 < LL; j0 += 64) {
        __syncthreads();
        *(float4*)&Ksh[lr     ][lc] = kA;
        *(float4*)&Ksh[lr + 32][lc] = kB;
        *(float4*)&Vsh[lr     ][lc] = vA;
        *(float4*)&Vsh[lr + 32][lc] = vB;
        __syncthreads();
        if (j0 + 64 < LL) {
            const float* kn = kg + (size_t)(j0 + 64)*HD;
            const float* vn = vg + (size_t)(j0 + 64)*HD;
            kA = *(const float4*)&kn[(lr     )*HD + lc];
            kB = *(const float4*)&kn[(lr + 32)*HD + lc];
            vA = *(const float4*)&vn[(lr     )*HD + lc];
            vB = *(const float4*)&vn[(lr + 32)*HD + lc];
        }

        // ---- S = mask + Q K^T ----
        float s[8][4];
        #pragma unroll
        for (int jn = 0; jn < 8; jn++) {
            float2 m0v = *(const float2*)&mr0[j0 + jn*8 + 2*qq];
            float2 m1v = *(const float2*)&mr1[j0 + jn*8 + 2*qq];
            s[jn][0] = m0v.x; s[jn][1] = m0v.y;
            s[jn][2] = m1v.x; s[jn][3] = m1v.y;
        }
        #pragma unroll
        for (int k = 0; k < 4; k++) {
            #pragma unroll
            for (int jn = 0; jn < 8; jn++) {
                unsigned b0 = __float_as_uint(Ksh[jn*8 + qr][k*8 + qq    ]);
                unsigned b1 = __float_as_uint(Ksh[jn*8 + qr][k*8 + qq + 4]);
                mma_tf32(s[jn], qA[k], b0, b1);
            }
        }

        // ---- online softmax ----
        float tm0 = -1e30f, tm1 = -1e30f;
        #pragma unroll
        for (int jn = 0; jn < 8; jn++) {
            tm0 = fmaxf(tm0, fmaxf(s[jn][0], s[jn][1]));
            tm1 = fmaxf(tm1, fmaxf(s[jn][2], s[jn][3]));
        }
        tm0 = fmaxf(tm0, __shfl_xor_sync(0xffffffffu, tm0, 1));
        tm0 = fmaxf(tm0, __shfl_xor_sync(0xffffffffu, tm0, 2));
        tm1 = fmaxf(tm1, __shfl_xor_sync(0xffffffffu, tm1, 1));
        tm1 = fmaxf(tm1, __shfl_xor_sync(0xffffffffu, tm1, 2));
        float nm0 = fmaxf(rm0, tm0), nm1 = fmaxf(rm1, tm1);
        float sc0 = __expf(rm0 - nm0), sc1 = __expf(rm1 - nm1);
        float ts0 = 0.f, ts1 = 0.f;
        #pragma unroll
        for (int jn = 0; jn < 8; jn++) {
            s[jn][0] = __expf(s[jn][0] - nm0);
            s[jn][1] = __expf(s[jn][1] - nm0);
            s[jn][2] = __expf(s[jn][2] - nm1);
            s[jn][3] = __expf(s[jn][3] - nm1);
            ts0 += s[jn][0] + s[jn][1];
            ts1 += s[jn][2] + s[jn][3];
        }
        ts0 += __shfl_xor_sync(0xffffffffu, ts0, 1);
        ts0 += __shfl_xor_sync(0xffffffffu, ts0, 2);
        ts1 += __shfl_xor_sync(0xffffffffu, ts1, 1);
        ts1 += __shfl_xor_sync(0xffffffffu, ts1, 2);
        sum0 = sum0*sc0 + ts0;  sum1 = sum1*sc1 + ts1;
        rm0 = nm0; rm1 = nm1;
        #pragma unroll
        for (int dn = 0; dn < 4; dn++) {
            o[dn][0] *= sc0; o[dn][1] *= sc0;
            o[dn][2] *= sc1; o[dn][3] *= sc1;
        }

        // ---- P -> shared (warp-local), fix fragment layout ----
        __syncwarp();
        #pragma unroll
        for (int jn = 0; jn < 8; jn++) {
            *(float2*)&Psh[pr    ][jn*8 + 2*qq] = make_float2(s[jn][0], s[jn][1]);
            *(float2*)&Psh[pr + 8][jn*8 + 2*qq] = make_float2(s[jn][2], s[jn][3]);
        }
        __syncwarp();

        // ---- O += P V : raw tf32 (P in [0,1], V raw) ----
        #pragma unroll
        for (int kk = 0; kk < 8; kk++) {
            unsigned a[4];
            a[0] = __float_as_uint(Psh[pr    ][kk*8 + qq    ]);
            a[1] = __float_as_uint(Psh[pr + 8][kk*8 + qq    ]);
            a[2] = __float_as_uint(Psh[pr    ][kk*8 + qq + 4]);
            a[3] = __float_as_uint(Psh[pr + 8][kk*8 + qq + 4]);
            #pragma unroll
            for (int dn = 0; dn < 4; dn++) {
                unsigned b0 = __float_as_uint(Vsh[kk*8 + qq    ][dn*8 + qr]);
                unsigned b1 = __float_as_uint(Vsh[kk*8 + qq + 4][dn*8 + qr]);
                mma_tf32(o[dn], a, b0, b1);
            }
        }
    }

    float inv0 = 1.f / sum0, inv1 = 1.f / sum1;
    float* og0 = g_attn + ((size_t)(bi*LL + row0    ))*CC + n*HD;
    float* og1 = g_attn + ((size_t)(bi*LL + row0 + 8))*CC + n*HD;
    #pragma unroll
    for (int dn = 0; dn < 4; dn++) {
        *(float2*)&og0[dn*8 + 2*qq] = make_float2(o[dn][0]*inv0, o[dn][1]*inv0);
        *(float2*)&og1[dn*8 + 2*qq] = make_float2(o[dn][2]*inv1, o[dn][3]*inv1);
    }
}

#define ATTN_SMEM ((2*64*KSTR + 128*PSTR) * 4)

// ---------------- launch -------------------------------------------------------
extern "C" void kernel_launch(void* const* d_in, const int* in_sizes, int n_in,
                              void* d_out, int out_size)
{
    const float* x    = (const float*)d_in[0];
    const float* sinv = (const float*)d_in[1];
    const float* cosv = (const float*)d_in[2];
    const float* mask = (const float*)d_in[3];
    const float* wq   = (const float*)d_in[4];
    const float* bq   = (const float*)d_in[5];
    const float* wk   = (const float*)d_in[6];
    const float* bk   = (const float*)d_in[7];
    const float* wv   = (const float*)d_in[8];
    const float* bv   = (const float*)d_in[9];
    const float* wdw  = (const float*)d_in[10];
    const float* bdw  = (const float*)d_in[11];
    const float* wo   = (const float*)d_in[12];
    const float* bo   = (const float*)d_in[13];
    float* out = (float*)d_out;

    cudaFuncSetAttribute(attn_mma, cudaFuncAttributeMaxDynamicSharedMemorySize,
                         ATTN_SMEM);
    cudaFuncSetAttribute(qkv_mma, cudaFuncAttributeMaxDynamicSharedMemorySize,
                         GEMM_SMEM);
    cudaFuncSetAttribute(out_mma, cudaFuncAttributeMaxDynamicSharedMemorySize,
                         GEMM_SMEM);

    qkv_mma<<<dim3(CC/128, MTOT/64, 3), 256, GEMM_SMEM>>>(x, wq, bq, wk, bk,
                                                          wv, bv, sinv, cosv);

    lepe_tiled<<<dim3(36, 4, BB), 256>>>(wdw, bdw);

    attn_mma<<<dim3(BB, LL/128, NHEAD), 256, ATTN_SMEM>>>(mask);

    out_mma<<<dim3(CC/128, MTOT/64), 256, GEMM_SMEM>>>(wo, bo, out);
}

// round 7
// speedup vs baseline: 3.6106x; 1.0254x over previous
#include <cuda_runtime.h>

#define BB    2
#define HH    48
#define WW    48
#define CC    256
#define NHEAD 8
#define HD    32
#define LL    (HH*WW)      /* 2304 */
#define MTOT  (BB*LL)      /* 4608 */

// ---------------- scratch (device globals; no allocs allowed) ----------------
__device__ float g_q   [BB*NHEAD*LL*HD];
__device__ float g_k   [BB*NHEAD*LL*HD];
__device__ float g_vh  [BB*NHEAD*LL*HD];
__device__ float g_vn  [BB*LL*CC];
__device__ float g_lepe[BB*LL*CC];
__device__ float g_attn[BB*LL*CC];

// ---------------- helpers ------------------------------------------------------
__device__ __forceinline__ void mma_tf32(float c[4], const unsigned a[4],
                                         unsigned b0, unsigned b1) {
    asm("mma.sync.aligned.m16n8k8.row.col.f32.tf32.tf32.f32 "
        "{%0,%1,%2,%3}, {%4,%5,%6,%7}, {%8,%9}, {%0,%1,%2,%3};"
        : "+f"(c[0]), "+f"(c[1]), "+f"(c[2]), "+f"(c[3])
        : "r"(a[0]), "r"(a[1]), "r"(a[2]), "r"(a[3]), "r"(b0), "r"(b1));
}
#define TF32_HI_MASK 0xFFFFE000u
__device__ __forceinline__ void hilo(float v, unsigned& hi, unsigned& lo) {
    unsigned u = __float_as_uint(v) & TF32_HI_MASK;
    hi = u;
    lo = __float_as_uint(v - __uint_as_float(u));
}
__device__ __forceinline__ unsigned smem_u32(const void* p) {
    return (unsigned)__cvta_generic_to_shared(p);
}
__device__ __forceinline__ void cp16(unsigned dst, const void* src) {
    asm volatile("cp.async.cg.shared.global [%0], [%1], 16;" :: "r"(dst), "l"(src));
}
#define CP_COMMIT() asm volatile("cp.async.commit_group;")
#define CP_WAIT0()  asm volatile("cp.async.wait_group 0;" ::: "memory")

// ---------------- tf32 MMA GEMM: 32x128 tiles, K=256, BK=32 --------------------
#define ASTR 36
#define BSTR 132

// QKV projection + bias + (rotary for q,k) + head-major scatter
__global__ __launch_bounds__(256) void qkv_mma(
    const float* __restrict__ x,
    const float* __restrict__ wq, const float* __restrict__ bq,
    const float* __restrict__ wk, const float* __restrict__ bk,
    const float* __restrict__ wv, const float* __restrict__ bv,
    const float* __restrict__ sinv, const float* __restrict__ cosv)
{
    const int z = blockIdx.z;
    const float* Wm   = (z == 0) ? wq : (z == 1) ? wk : wv;
    const float* bias = (z == 0) ? bq : (z == 1) ? bk : bv;

    __shared__ __align__(16) float As[32][ASTR];
    __shared__ __align__(16) float Bs[32][BSTR];

    const int t = threadIdx.x, lane = t & 31, warp = t >> 5;
    const int qr = lane >> 2, qq = lane & 3;
    const int wm = warp >> 2, wn = warp & 3;      // 2m x 4n warps, warp = 16x32
    const int m0 = blockIdx.y * 32;
    const int n0 = blockIdx.x * 128;

    const int ar = t >> 3, ac = (t & 7) * 4;      // A: one float4 per thread
    const int bkr = warp, bnc = lane * 4;         // B: rows bkr + u*8

    float acc[4][4];
    #pragma unroll
    for (int j = 0; j < 4; j++)
        #pragma unroll
        for (int r = 0; r < 4; r++) acc[j][r] = 0.f;

    float4 aA, b4[4];
    aA = *(const float4*)&x[(m0 + ar)*CC + ac];
    #pragma unroll
    for (int u = 0; u < 4; u++)
        b4[u] = *(const float4*)&Wm[(bkr + u*8)*CC + n0 + bnc];

    for (int it = 0; it < 8; it++) {
        if (it) __syncthreads();
        *(float4*)&As[ar][ac] = aA;
        #pragma unroll
        for (int u = 0; u < 4; u++)
            *(float4*)&Bs[bkr + u*8][bnc] = b4[u];
        __syncthreads();
        if (it < 7) {
            int k0 = (it + 1) * 32;
            aA = *(const float4*)&x[(m0 + ar)*CC + k0 + ac];
            #pragma unroll
            for (int u = 0; u < 4; u++)
                b4[u] = *(const float4*)&Wm[(k0 + bkr + u*8)*CC + n0 + bnc];
        }
        #pragma unroll
        for (int kb = 0; kb < 4; kb++) {
            unsigned ahi[4], alo[4];
            int arow = wm*16 + qr;
            float a0 = As[arow    ][kb*8 + qq];
            float a1 = As[arow + 8][kb*8 + qq];
            float a2 = As[arow    ][kb*8 + qq + 4];
            float a3 = As[arow + 8][kb*8 + qq + 4];
            hilo(a0, ahi[0], alo[0]); hilo(a1, ahi[1], alo[1]);
            hilo(a2, ahi[2], alo[2]); hilo(a3, ahi[3], alo[3]);
            #pragma unroll
            for (int nf = 0; nf < 4; nf++) {
                int bcol = wn*32 + nf*8 + qr;
                float b0 = Bs[kb*8 + qq    ][bcol];
                float b1 = Bs[kb*8 + qq + 4][bcol];
                unsigned bh0, bl0, bh1, bl1;
                hilo(b0, bh0, bl0); hilo(b1, bh1, bl1);
                mma_tf32(acc[nf], ahi, bh0, bh1);
                mma_tf32(acc[nf], alo, bh0, bh1);
                mma_tf32(acc[nf], ahi, bl0, bl1);
            }
        }
    }

    const float scaling = 0.17677669529663687f;
    #pragma unroll
    for (int nf = 0; nf < 4; nf++) {
        int cbase = n0 + wn*32 + nf*8 + 2*qq;
        int n = cbase >> 5, d = cbase & 31;
        #pragma unroll
        for (int rr = 0; rr < 2; rr++) {
            int m = m0 + wm*16 + qr + rr*8;
            int bi = m / LL, l = m - bi*LL;
            float e = acc[nf][rr*2 + 0] + __ldg(&bias[cbase]);
            float o = acc[nf][rr*2 + 1] + __ldg(&bias[cbase + 1]);
            if (z == 1) { e *= scaling; o *= scaling; }
            if (z != 2) {
                float2 sv = *(const float2*)&sinv[l*HD + d];
                float2 cv = *(const float2*)&cosv[l*HD + d];
                float e2 = e*cv.x - o*sv.x;
                float o2 = o*cv.y + e*sv.y;
                e = e2; o = o2;
            }
            size_t idx = ((size_t)(bi*NHEAD + n)*LL + l)*HD + d;
            if (z == 0)      *(float2*)&g_q[idx] = make_float2(e, o);
            else if (z == 1) *(float2*)&g_k[idx] = make_float2(e, o);
            else {
                *(float2*)&g_vh[idx] = make_float2(e, o);
                *(float2*)&g_vn[((size_t)(bi*LL + l))*CC + cbase] =
                    make_float2(e, o);
            }
        }
    }
}

// output projection: (attn + lepe) @ wo + bo
__global__ __launch_bounds__(256) void out_mma(const float* __restrict__ wo,
                                               const float* __restrict__ bo,
                                               float* __restrict__ out)
{
    __shared__ __align__(16) float As[32][ASTR];
    __shared__ __align__(16) float Bs[32][BSTR];

    const int t = threadIdx.x, lane = t & 31, warp = t >> 5;
    const int qr = lane >> 2, qq = lane & 3;
    const int wm = warp >> 2, wn = warp & 3;
    const int m0 = blockIdx.y * 32;
    const int n0 = blockIdx.x * 128;

    const int ar = t >> 3, ac = (t & 7) * 4;
    const int bkr = warp, bnc = lane * 4;

    float acc[4][4];
    #pragma unroll
    for (int j = 0; j < 4; j++)
        #pragma unroll
        for (int r = 0; r < 4; r++) acc[j][r] = 0.f;

    float4 aA, b4[4];
    {
        float4 u1 = *(const float4*)&g_attn[(m0 + ar)*CC + ac];
        float4 u2 = *(const float4*)&g_lepe[(m0 + ar)*CC + ac];
        aA = make_float4(u1.x+u2.x, u1.y+u2.y, u1.z+u2.z, u1.w+u2.w);
    }
    #pragma unroll
    for (int u = 0; u < 4; u++)
        b4[u] = *(const float4*)&wo[(bkr + u*8)*CC + n0 + bnc];

    for (int it = 0; it < 8; it++) {
        if (it) __syncthreads();
        *(float4*)&As[ar][ac] = aA;
        #pragma unroll
        for (int u = 0; u < 4; u++)
            *(float4*)&Bs[bkr + u*8][bnc] = b4[u];
        __syncthreads();
        if (it < 7) {
            int k0 = (it + 1) * 32;
            float4 u1 = *(const float4*)&g_attn[(m0 + ar)*CC + k0 + ac];
            float4 u2 = *(const float4*)&g_lepe[(m0 + ar)*CC + k0 + ac];
            aA = make_float4(u1.x+u2.x, u1.y+u2.y, u1.z+u2.z, u1.w+u2.w);
            #pragma unroll
            for (int u = 0; u < 4; u++)
                b4[u] = *(const float4*)&wo[(k0 + bkr + u*8)*CC + n0 + bnc];
        }
        #pragma unroll
        for (int kb = 0; kb < 4; kb++) {
            unsigned ahi[4], alo[4];
            int arow = wm*16 + qr;
            float a0 = As[arow    ][kb*8 + qq];
            float a1 = As[arow + 8][kb*8 + qq];
            float a2 = As[arow    ][kb*8 + qq + 4];
            float a3 = As[arow + 8][kb*8 + qq + 4];
            hilo(a0, ahi[0], alo[0]); hilo(a1, ahi[1], alo[1]);
            hilo(a2, ahi[2], alo[2]); hilo(a3, ahi[3], alo[3]);
            #pragma unroll
            for (int nf = 0; nf < 4; nf++) {
                int bcol = wn*32 + nf*8 + qr;
                float b0 = Bs[kb*8 + qq    ][bcol];
                float b1 = Bs[kb*8 + qq + 4][bcol];
                unsigned bh0, bl0, bh1, bl1;
                hilo(b0, bh0, bl0); hilo(b1, bh1, bl1);
                mma_tf32(acc[nf], ahi, bh0, bh1);
                mma_tf32(acc[nf], alo, bh0, bh1);
                mma_tf32(acc[nf], ahi, bl0, bl1);
            }
        }
    }

    #pragma unroll
    for (int nf = 0; nf < 4; nf++) {
        int cbase = n0 + wn*32 + nf*8 + 2*qq;
        float bx = __ldg(&bo[cbase]), by = __ldg(&bo[cbase + 1]);
        #pragma unroll
        for (int rr = 0; rr < 2; rr++) {
            int m = m0 + wm*16 + qr + rr*8;
            *(float2*)&out[(size_t)m*CC + cbase] =
                make_float2(acc[nf][rr*2] + bx, acc[nf][rr*2 + 1] + by);
        }
    }
}

// ---------------- 5x5 depthwise conv (LEPE), smem-tiled ------------------------
__global__ __launch_bounds__(256) void lepe_tiled(const float* __restrict__ wdw,
                                                  const float* __restrict__ bdw)
{
    __shared__ float patch[12*12*64];

    const int t  = threadIdx.x;
    const int tx = blockIdx.x % 6, ty = blockIdx.x / 6;
    const int cg = blockIdx.y;
    const int bi = blockIdx.z;
    const int h0 = ty*8, w0 = tx*8;
    const int c0 = cg*64;

    #pragma unroll
    for (int i = 0; i < 9; i++) {
        int fidx = t + i*256;
        int c4  = (fidx & 15) * 4;
        int pix = fidx >> 4;
        int py = pix / 12, px = pix % 12;
        int hy = h0 + py - 2, wx = w0 + px - 2;
        float4 v = make_float4(0.f, 0.f, 0.f, 0.f);
        if (hy >= 0 && hy < HH && wx >= 0 && wx < WW)
            v = *(const float4*)&g_vn[((size_t)(bi*LL + hy*WW + wx))*CC + c0 + c4];
        *(float4*)&patch[(py*12 + px)*64 + c4] = v;
    }

    const int c  = t & 63;
    const int pg = t >> 6;
    float wr[25];
    #pragma unroll
    for (int i = 0; i < 25; i++) wr[i] = __ldg(&wdw[i*CC + c0 + c]);
    const float bias = __ldg(&bdw[c0 + c]);

    __syncthreads();

    #pragma unroll
    for (int j = 0; j < 16; j++) {
        int pid = pg*16 + j;
        int py = pid >> 3, px = pid & 7;
        float acc = bias;
        #pragma unroll
        for (int dy = 0; dy < 5; dy++)
            #pragma unroll
            for (int dx = 0; dx < 5; dx++)
                acc += patch[((py+dy)*12 + (px+dx))*64 + c] * wr[dy*5+dx];
        g_lepe[((size_t)(bi*LL + (h0+py)*WW + (w0+px)))*CC + c0 + c] = acc;
    }
}

// ---------------- flash attention: cp.async pipeline + mask-in-accumulator -----
#define KSTR 36
#define PSTR 68
#define KVSZ (64*KSTR)                  /* floats per K/V stage */
#define ATTN_SMEM ((4*KVSZ + 128*PSTR) * 4)

__global__ __launch_bounds__(256, 2) void attn_mma(const float* __restrict__ mask)
{
    extern __shared__ __align__(16) float smem[];
    float* Kst[2] = { smem,          smem + KVSZ   };
    float* Vst[2] = { smem + 2*KVSZ, smem + 3*KVSZ };
    float (*Psh)[PSTR] = (float(*)[PSTR])(smem + 4*KVSZ);

    const int bi = blockIdx.x;
    const int l0 = blockIdx.y * 128;
    const int n  = blockIdx.z;
    const int t = threadIdx.x, lane = t & 31, warp = t >> 5;
    const int qr = lane >> 2, qq = lane & 3;

    const int bn = bi*NHEAD + n;
    const float* qg = g_q  + (size_t)bn*LL*HD;
    const float* kg = g_k  + (size_t)bn*LL*HD;
    const float* vg = g_vh + (size_t)bn*LL*HD;

    const int row0 = l0 + warp*16 + qr;
    const float* mr0 = mask + (size_t)n*LL*LL + (size_t)row0*LL;
    const float* mr1 = mr0 + (size_t)8*LL;

    // cp.async load slots: each thread does rows lr, lr+32 for K and V
    const int lr = t >> 3, lc = (t & 7) * 4;
    unsigned kd0[2], kd1[2], vd0[2], vd1[2];
    #pragma unroll
    for (int s = 0; s < 2; s++) {
        kd0[s] = smem_u32(&Kst[s][lr*KSTR + lc]);
        kd1[s] = smem_u32(&Kst[s][(lr + 32)*KSTR + lc]);
        vd0[s] = smem_u32(&Vst[s][lr*KSTR + lc]);
        vd1[s] = smem_u32(&Vst[s][(lr + 32)*KSTR + lc]);
    }

    // issue tile 0
    cp16(kd0[0], &kg[(size_t)lr*HD + lc]);
    cp16(kd1[0], &kg[(size_t)(lr + 32)*HD + lc]);
    cp16(vd0[0], &vg[(size_t)lr*HD + lc]);
    cp16(vd1[0], &vg[(size_t)(lr + 32)*HD + lc]);
    CP_COMMIT();

    // preload Q A-fragments
    unsigned qA[4][4];
    #pragma unroll
    for (int k = 0; k < 4; k++) {
        qA[k][0] = __float_as_uint(qg[(row0  )*HD + k*8 + qq    ]);
        qA[k][1] = __float_as_uint(qg[(row0+8)*HD + k*8 + qq    ]);
        qA[k][2] = __float_as_uint(qg[(row0  )*HD + k*8 + qq + 4]);
        qA[k][3] = __float_as_uint(qg[(row0+8)*HD + k*8 + qq + 4]);
    }

    // s starts as the mask tile (accumulator-init trick)
    float s[8][4];
    #pragma unroll
    for (int jn = 0; jn < 8; jn++) {
        float2 m0v = __ldg((const float2*)&mr0[jn*8 + 2*qq]);
        float2 m1v = __ldg((const float2*)&mr1[jn*8 + 2*qq]);
        s[jn][0] = m0v.x; s[jn][1] = m0v.y;
        s[jn][2] = m1v.x; s[jn][3] = m1v.y;
    }

    float o[4][4];
    #pragma unroll
    for (int i = 0; i < 4; i++)
        #pragma unroll
        for (int j = 0; j < 4; j++) o[i][j] = 0.f;
    float rm0 = -1e30f, rm1 = -1e30f, sum0 = 0.f, sum1 = 0.f;
    const int pr = warp*16 + qr;

    for (int tix = 0; tix < LL/64; tix++) {
        const int cur = tix & 1;
        const int j0 = tix * 64;
        CP_WAIT0();
        __syncthreads();        // tile tix visible to all; prev-stage reads done
        if (tix + 1 < LL/64) {
            const float* kn = kg + (size_t)(j0 + 64)*HD;
            const float* vn = vg + (size_t)(j0 + 64)*HD;
            int nxt = cur ^ 1;
            cp16(kd0[nxt], &kn[(size_t)lr*HD + lc]);
            cp16(kd1[nxt], &kn[(size_t)(lr + 32)*HD + lc]);
            cp16(vd0[nxt], &vn[(size_t)lr*HD + lc]);
            cp16(vd1[nxt], &vn[(size_t)(lr + 32)*HD + lc]);
            CP_COMMIT();
        }
        const float* Ksh = Kst[cur];
        const float* Vsh = Vst[cur];

        // ---- S = mask + Q K^T  (s already holds mask) ----
        #pragma unroll
        for (int k = 0; k < 4; k++) {
            #pragma unroll
            for (int jn = 0; jn < 8; jn++) {
                unsigned b0 = __float_as_uint(Ksh[(jn*8 + qr)*KSTR + k*8 + qq    ]);
                unsigned b1 = __float_as_uint(Ksh[(jn*8 + qr)*KSTR + k*8 + qq + 4]);
                mma_tf32(s[jn], qA[k], b0, b1);
            }
        }

        // ---- online softmax ----
        float tm0 = -1e30f, tm1 = -1e30f;
        #pragma unroll
        for (int jn = 0; jn < 8; jn++) {
            tm0 = fmaxf(tm0, fmaxf(s[jn][0], s[jn][1]));
            tm1 = fmaxf(tm1, fmaxf(s[jn][2], s[jn][3]));
        }
        tm0 = fmaxf(tm0, __shfl_xor_sync(0xffffffffu, tm0, 1));
        tm0 = fmaxf(tm0, __shfl_xor_sync(0xffffffffu, tm0, 2));
        tm1 = fmaxf(tm1, __shfl_xor_sync(0xffffffffu, tm1, 1));
        tm1 = fmaxf(tm1, __shfl_xor_sync(0xffffffffu, tm1, 2));
        float nm0 = fmaxf(rm0, tm0), nm1 = fmaxf(rm1, tm1);
        float sc0 = __expf(rm0 - nm0), sc1 = __expf(rm1 - nm1);
        float ts0 = 0.f, ts1 = 0.f;
        #pragma unroll
        for (int jn = 0; jn < 8; jn++) {
            s[jn][0] = __expf(s[jn][0] - nm0);
            s[jn][1] = __expf(s[jn][1] - nm0);
            s[jn][2] = __expf(s[jn][2] - nm1);
            s[jn][3] = __expf(s[jn][3] - nm1);
            ts0 += s[jn][0] + s[jn][1];
            ts1 += s[jn][2] + s[jn][3];
        }
        ts0 += __shfl_xor_sync(0xffffffffu, ts0, 1);
        ts0 += __shfl_xor_sync(0xffffffffu, ts0, 2);
        ts1 += __shfl_xor_sync(0xffffffffu, ts1, 1);
        ts1 += __shfl_xor_sync(0xffffffffu, ts1, 2);
        sum0 = sum0*sc0 + ts0;  sum1 = sum1*sc1 + ts1;
        rm0 = nm0; rm1 = nm1;
        #pragma unroll
        for (int dn = 0; dn < 4; dn++) {
            o[dn][0] *= sc0; o[dn][1] *= sc0;
            o[dn][2] *= sc1; o[dn][3] *= sc1;
        }

        // ---- P -> shared (warp-local) ----
        #pragma unroll
        for (int jn = 0; jn < 8; jn++) {
            *(float2*)&Psh[pr    ][jn*8 + 2*qq] = make_float2(s[jn][0], s[jn][1]);
            *(float2*)&Psh[pr + 8][jn*8 + 2*qq] = make_float2(s[jn][2], s[jn][3]);
        }
        __syncwarp();

        // ---- s regs now dead: prefetch NEXT tile's mask into them ----
        if (tix + 1 < LL/64) {
            const int j0n = j0 + 64;
            #pragma unroll
            for (int jn = 0; jn < 8; jn++) {
                float2 m0v = __ldg((const float2*)&mr0[j0n + jn*8 + 2*qq]);
                float2 m1v = __ldg((const float2*)&mr1[j0n + jn*8 + 2*qq]);
                s[jn][0] = m0v.x; s[jn][1] = m0v.y;
                s[jn][2] = m1v.x; s[jn][3] = m1v.y;
            }
        }

        // ---- O += P V (raw tf32) ----
        #pragma unroll
        for (int kk = 0; kk < 8; kk++) {
            unsigned a[4];
            a[0] = __float_as_uint(Psh[pr    ][kk*8 + qq    ]);
            a[1] = __float_as_uint(Psh[pr + 8][kk*8 + qq    ]);
            a[2] = __float_as_uint(Psh[pr    ][kk*8 + qq + 4]);
            a[3] = __float_as_uint(Psh[pr + 8][kk*8 + qq + 4]);
            #pragma unroll
            for (int dn = 0; dn < 4; dn++) {
                unsigned b0 = __float_as_uint(Vsh[(kk*8 + qq    )*KSTR + dn*8 + qr]);
                unsigned b1 = __float_as_uint(Vsh[(kk*8 + qq + 4)*KSTR + dn*8 + qr]);
                mma_tf32(o[dn], a, b0, b1);
            }
        }
    }

    float inv0 = 1.f / sum0, inv1 = 1.f / sum1;
    float* og0 = g_attn + ((size_t)(bi*LL + row0    ))*CC + n*HD;
    float* og1 = g_attn + ((size_t)(bi*LL + row0 + 8))*CC + n*HD;
    #pragma unroll
    for (int dn = 0; dn < 4; dn++) {
        *(float2*)&og0[dn*8 + 2*qq] = make_float2(o[dn][0]*inv0, o[dn][1]*inv0);
        *(float2*)&og1[dn*8 + 2*qq] = make_float2(o[dn][2]*inv1, o[dn][3]*inv1);
    }
}

// ---------------- launch -------------------------------------------------------
extern "C" void kernel_launch(void* const* d_in, const int* in_sizes, int n_in,
                              void* d_out, int out_size)
{
    const float* x    = (const float*)d_in[0];
    const float* sinv = (const float*)d_in[1];
    const float* cosv = (const float*)d_in[2];
    const float* mask = (const float*)d_in[3];
    const float* wq   = (const float*)d_in[4];
    const float* bq   = (const float*)d_in[5];
    const float* wk   = (const float*)d_in[6];
    const float* bk   = (const float*)d_in[7];
    const float* wv   = (const float*)d_in[8];
    const float* bv   = (const float*)d_in[9];
    const float* wdw  = (const float*)d_in[10];
    const float* bdw  = (const float*)d_in[11];
    const float* wo   = (const float*)d_in[12];
    const float* bo   = (const float*)d_in[13];
    float* out = (float*)d_out;

    cudaFuncSetAttribute(attn_mma, cudaFuncAttributeMaxDynamicSharedMemorySize,
                         ATTN_SMEM);

    qkv_mma<<<dim3(CC/128, MTOT/32, 3), 256>>>(x, wq, bq, wk, bk, wv, bv,
                                               sinv, cosv);

    lepe_tiled<<<dim3(36, 4, BB), 256>>>(wdw, bdw);

    attn_mma<<<dim3(BB, LL/128, NHEAD), 256, ATTN_SMEM>>>(mask);

    out_mma<<<dim3(CC/128, MTOT/32), 256>>>(wo, bo, out);
}